// round 14
// baseline (speedup 1.0000x reference)
#include <cuda_runtime.h>
#include <cuda_bf16.h>
#include <cstdint>

// Problem constants
constexpr int B  = 8;
constexpr int C  = 256;
constexpr int CQ = 128;
constexpr int N  = 4096;   // 64*64

// Scratch (device globals)
__device__ __align__(16) __nv_bfloat16 g_xb[B * C * N];            // x bf16, c-major
__device__ __align__(16) __nv_bfloat16 g_qkv[(size_t)B * 512 * N]; // rows: 0-127 q, 128-255 k, 256-511 v
__device__ __align__(16) __nv_bfloat16 g_E[(size_t)B * N * N];     // exp(S), bf16, 268 MB
__device__ float g_part[B * 32 * N];                               // per-mblock col sums
__device__ __align__(16) __nv_bfloat16 g_Wt[C * 512];              // concat W^T [C][512]
__device__ float g_bqkv[512];

// ---------------------------------------------------------------------------
// helpers
// ---------------------------------------------------------------------------
__device__ __forceinline__ uint32_t su(const void* p) {
    return (uint32_t)__cvta_generic_to_shared(p);
}
__device__ __forceinline__ void ldsm_x4(uint32_t* d, uint32_t addr) {
    asm volatile("ldmatrix.sync.aligned.m8n8.x4.shared.b16 {%0,%1,%2,%3}, [%4];\n"
                 : "=r"(d[0]), "=r"(d[1]), "=r"(d[2]), "=r"(d[3]) : "r"(addr));
}
__device__ __forceinline__ void ldsm_x4_t(uint32_t* d, uint32_t addr) {
    asm volatile("ldmatrix.sync.aligned.m8n8.x4.trans.shared.b16 {%0,%1,%2,%3}, [%4];\n"
                 : "=r"(d[0]), "=r"(d[1]), "=r"(d[2]), "=r"(d[3]) : "r"(addr));
}
__device__ __forceinline__ void mma_bf16(float* c, const uint32_t* a, const uint32_t* b) {
    asm volatile(
        "mma.sync.aligned.m16n8k16.row.col.f32.bf16.bf16.f32 "
        "{%0,%1,%2,%3}, {%4,%5,%6,%7}, {%8,%9}, {%0,%1,%2,%3};\n"
        : "+f"(c[0]), "+f"(c[1]), "+f"(c[2]), "+f"(c[3])
        : "r"(a[0]), "r"(a[1]), "r"(a[2]), "r"(a[3]), "r"(b[0]), "r"(b[1]));
}
#define CP_ASYNC16(dst, src) \
    asm volatile("cp.async.cg.shared.global [%0], [%1], 16;\n" :: "r"(dst), "l"(src))
#define CP_COMMIT() asm volatile("cp.async.commit_group;\n" ::: "memory")

// ---------------------------------------------------------------------------
// prep: x -> bf16 (float4)  |  Wq/Wk/Wv -> concat transposed bf16  |  biases
// ---------------------------------------------------------------------------
constexpr int PREP_X_BLOCKS = B * C * N / 4 / 256;   // 8192
constexpr int PREP_W_BLOCKS = (C * 512) / 256;       // 512
constexpr int PREP_BLOCKS = PREP_X_BLOCKS + PREP_W_BLOCKS + 2;

__global__ void prep_kernel(const float* __restrict__ x,
                            const float* __restrict__ Wq, const float* __restrict__ Wk,
                            const float* __restrict__ Wv,
                            const float* __restrict__ bq, const float* __restrict__ bk,
                            const float* __restrict__ bv)
{
    const int bid = blockIdx.x;
    if (bid < PREP_X_BLOCKS) {
        const int idx = bid * 256 + threadIdx.x;
        const float4 v = reinterpret_cast<const float4*>(x)[idx];
        __nv_bfloat162 h0 = __floats2bfloat162_rn(v.x, v.y);
        __nv_bfloat162 h1 = __floats2bfloat162_rn(v.z, v.w);
        reinterpret_cast<uint2*>(g_xb)[idx] =
            make_uint2(*reinterpret_cast<uint32_t*>(&h0), *reinterpret_cast<uint32_t*>(&h1));
    } else if (bid < PREP_X_BLOCKS + PREP_W_BLOCKS) {
        const int idx = (bid - PREP_X_BLOCKS) * 256 + threadIdx.x;  // 0 .. 131071
        if (idx < 32768) {                 // Wq -> cols 0..127
            const int c = idx >> 7, o = idx & 127;
            g_Wt[c * 512 + o] = __float2bfloat16(Wq[o * C + c]);
        } else if (idx < 65536) {          // Wk -> cols 128..255
            const int j = idx - 32768;
            const int c = j >> 7, o = j & 127;
            g_Wt[c * 512 + 128 + o] = __float2bfloat16(Wk[o * C + c]);
        } else {                           // Wv -> cols 256..511
            const int j = idx - 65536;
            const int c = j >> 8, o = j & 255;
            g_Wt[c * 512 + 256 + o] = __float2bfloat16(Wv[o * C + c]);
        }
    } else {
        const int i = (bid - PREP_X_BLOCKS - PREP_W_BLOCKS) * 256 + threadIdx.x;
        if (i < 512)
            g_bqkv[i] = (i < 128) ? bq[i] : (i < 256) ? bk[i - 128] : bv[i - 256];
    }
}

// ---------------------------------------------------------------------------
// reduce partial column sums -> cinv (smem), then scale 64 v rows in place.
// grid (N/128, 4 row-groups, HB); batch = blockIdx.z + b0
// ---------------------------------------------------------------------------
__global__ __launch_bounds__(256) void finalize_v_kernel(int b0)
{
    __shared__ float s_cinv[128];
    const int b = blockIdx.z + b0;
    const int n0 = blockIdx.x * 128;
    const int r0 = blockIdx.y * 64;
    const int t = threadIdx.x;

    {
        const int col = t & 127, half = t >> 7;
        const float* p = g_part + ((size_t)b * 32 + half * 16) * N + n0 + col;
        float z = 0.f;
#pragma unroll
        for (int i = 0; i < 16; i++) z += p[(size_t)i * N];
        __shared__ float red[2][128];
        red[half][col] = z;
        __syncthreads();
        if (t < 128) s_cinv[t] = 1.0f / (red[0][t] + red[1][t]);
        __syncthreads();
    }

    __nv_bfloat16* vb = g_qkv + (size_t)b * 512 * N + (size_t)(256 + r0) * N;
    const int col32 = t & 63;
    const int rgrp = t >> 6;
    const float c0 = s_cinv[col32 * 2];
    const float c1 = s_cinv[col32 * 2 + 1];
#pragma unroll
    for (int r = rgrp; r < 64; r += 4) {
        uint32_t* p = reinterpret_cast<uint32_t*>(vb + (size_t)r * N + n0) + col32;
        const __nv_bfloat162 v = *reinterpret_cast<const __nv_bfloat162*>(p);
        *reinterpret_cast<__nv_bfloat162*>(p) =
            __floats2bfloat162_rn(__bfloat162float(v.x) * c0, __bfloat162float(v.y) * c1);
    }
}

// ---------------------------------------------------------------------------
// TN GEMM (both operands k-major), cp.async 4-stage, one sync per k-chunk.
// 256 threads, block 128x128, warps 2(m) x 4(n), warp tile 64x32, 2 blocks/SM.
// EPI 0: + bias[row], bf16 store              (merged qkv projection)
// EPI 1: exp(acc), bf16 store E, f32 partial column sums -> g_part  (QK)
// ---------------------------------------------------------------------------
constexpr int TN_STAGE = 17408;   // A 8704 + B 8704, row stride 272 B
constexpr int TN_SMEM = 4 * TN_STAGE;   // 69632

template <int EPI>
__global__ __launch_bounds__(256, 2) void gemm_tn_kernel(
    const __nv_bfloat16* __restrict__ Ag, const __nv_bfloat16* __restrict__ Bg,
    __nv_bfloat16* __restrict__ Cg, const float* __restrict__ bias,
    int K, int lda, int ldb, int ldc,
    long long sA, long long sB, long long sC, int b0)
{
    extern __shared__ __align__(16) uint8_t dsm[];
    __shared__ float s_col[2][128];

    Ag += (long long)blockIdx.z * sA;
    Bg += (long long)blockIdx.z * sB;
    Cg += (long long)blockIdx.z * sC;

    const int m0 = blockIdx.y * 128;
    const int n0 = blockIdx.x * 128;
    const int tid = threadIdx.x;
    const int lane = tid & 31, wid = tid >> 5;
    const int wm = wid >> 2, wn = wid & 3;
    const int mB = wm * 64, nB = wn * 32;
    const int q = lane >> 3, lr = lane & 7;

    float acc[4][4][4] = {};

    const int chunk = tid & 15, row = tid >> 4;   // row 0..15
    const uint32_t sbase = su(dsm);
    const int Kt = K >> 5;

    for (int kt = 0; kt < Kt + 2; kt++) {
        if (kt < Kt) {
            const uint32_t sb = sbase + (kt & 3) * TN_STAGE;
            const __nv_bfloat16* As = Ag + (size_t)(kt * 32 + row) * lda + m0 + chunk * 8;
            const __nv_bfloat16* Bs = Bg + (size_t)(kt * 32 + row) * ldb + n0 + chunk * 8;
            CP_ASYNC16(sb + row * 272 + chunk * 16, As);
            CP_ASYNC16(sb + (row + 16) * 272 + chunk * 16, As + (size_t)16 * lda);
            CP_ASYNC16(sb + 8704 + row * 272 + chunk * 16, Bs);
            CP_ASYNC16(sb + 8704 + (row + 16) * 272 + chunk * 16, Bs + (size_t)16 * ldb);
            CP_COMMIT();
        }
        if (kt >= 2) {
            if (kt < Kt)       asm volatile("cp.async.wait_group 2;\n" ::: "memory");
            else if (kt == Kt) asm volatile("cp.async.wait_group 1;\n" ::: "memory");
            else               asm volatile("cp.async.wait_group 0;\n" ::: "memory");
            __syncthreads();   // 4-stage ring: single barrier suffices
            const uint32_t sb = sbase + ((kt - 2) & 3) * TN_STAGE;
#pragma unroll
            for (int ks = 0; ks < 2; ks++) {
                const int kk = ks * 16;
                uint32_t Af[4][4], Bf[2][4];
#pragma unroll
                for (int im = 0; im < 4; im++)
                    ldsm_x4_t(Af[im], sb + (kk + ((q >> 1) << 3) + lr) * 272
                                         + (mB + im * 16 + ((q & 1) << 3)) * 2);
#pragma unroll
                for (int ib = 0; ib < 2; ib++)
                    ldsm_x4_t(Bf[ib], sb + 8704 + (kk + ((q & 1) << 3) + lr) * 272
                                         + (nB + ib * 16 + ((q >> 1) << 3)) * 2);
#pragma unroll
                for (int im = 0; im < 4; im++)
#pragma unroll
                    for (int in2 = 0; in2 < 4; in2++) {
                        uint32_t bfr[2] = { Bf[in2 >> 1][(in2 & 1) * 2],
                                            Bf[in2 >> 1][(in2 & 1) * 2 + 1] };
                        mma_bf16(acc[im][in2], Af[im], bfr);
                    }
            }
        }
    }

    const int g = lane >> 2, tg = lane & 3;

    if (EPI == 0) {
#pragma unroll
        for (int im = 0; im < 4; im++) {
            const int gm = m0 + mB + im * 16 + g;
            const float b0f = bias[gm], b1f = bias[gm + 8];
#pragma unroll
            for (int in2 = 0; in2 < 4; in2++) {
                const int col = n0 + nB + in2 * 8 + tg * 2;
                *reinterpret_cast<__nv_bfloat162*>(Cg + (size_t)gm * ldc + col) =
                    __floats2bfloat162_rn(acc[im][in2][0] + b0f, acc[im][in2][1] + b0f);
                *reinterpret_cast<__nv_bfloat162*>(Cg + (size_t)(gm + 8) * ldc + col) =
                    __floats2bfloat162_rn(acc[im][in2][2] + b1f, acc[im][in2][3] + b1f);
            }
        }
    } else {
        float s[4][2] = {};
#pragma unroll
        for (int im = 0; im < 4; im++) {
            const int gm = m0 + mB + im * 16 + g;
#pragma unroll
            for (int in2 = 0; in2 < 4; in2++) {
                const int col = n0 + nB + in2 * 8 + tg * 2;
                const float e0 = __expf(acc[im][in2][0]);
                const float e1 = __expf(acc[im][in2][1]);
                const float e2 = __expf(acc[im][in2][2]);
                const float e3 = __expf(acc[im][in2][3]);
                *reinterpret_cast<__nv_bfloat162*>(Cg + (size_t)gm * ldc + col) =
                    __floats2bfloat162_rn(e0, e1);
                *reinterpret_cast<__nv_bfloat162*>(Cg + (size_t)(gm + 8) * ldc + col) =
                    __floats2bfloat162_rn(e2, e3);
                s[in2][0] += e0 + e2;
                s[in2][1] += e1 + e3;
            }
        }
#pragma unroll
        for (int in2 = 0; in2 < 4; in2++)
#pragma unroll
            for (int j = 0; j < 2; j++) {
                float v = s[in2][j];
                v += __shfl_xor_sync(0xFFFFFFFF, v, 4);
                v += __shfl_xor_sync(0xFFFFFFFF, v, 8);
                v += __shfl_xor_sync(0xFFFFFFFF, v, 16);
                s[in2][j] = v;
            }
        if (lane < 4) {
#pragma unroll
            for (int in2 = 0; in2 < 4; in2++)
#pragma unroll
                for (int j = 0; j < 2; j++)
                    s_col[wm][nB + in2 * 8 + lane * 2 + j] = s[in2][j];
        }
        __syncthreads();
        if (tid < 128) {
            const float z = s_col[0][tid] + s_col[1][tid];
            g_part[((size_t)(blockIdx.z + b0) * 32 + blockIdx.y) * N + n0 + tid] = z;
        }
    }
}

// ---------------------------------------------------------------------------
// NT GEMM (AV): out[c][m] = gamma * sum_n V'[c][n] * E[m][n] + x[c][m]
// 256 threads, warp tile 64x32, block 128x128, BK=64, cp.async 3-stage,
// two barriers per chunk (3-ring rewrite hazard). 2 blocks/SM by smem.
// ---------------------------------------------------------------------------
constexpr int NT_ROW = 144;                  // 128 B data + 16 B pad
constexpr int NT_HALF = 128 * NT_ROW;        // 18432 B (one matrix)
constexpr int NT_STAGE = 2 * NT_HALF;        // 36864
constexpr int NT_SMEM = 3 * NT_STAGE;        // 110592

__global__ __launch_bounds__(256, 2) void gemm_nt_kernel(
    const float* __restrict__ x, const float* __restrict__ gamma,
    float* __restrict__ out, int b0)
{
    extern __shared__ __align__(16) uint8_t dsm[];

    const int b = blockIdx.z + b0;
    const __nv_bfloat16* Vb = g_qkv + (size_t)b * 512 * N + (size_t)256 * N;
    const __nv_bfloat16* Eb = g_E + (size_t)b * N * N;
    const float* xb = x + (size_t)b * C * N;
    float* ob = out + (size_t)b * C * N;

    const int c0 = blockIdx.y * 128;
    const int m0 = blockIdx.x * 128;
    const int tid = threadIdx.x;
    const int lane = tid & 31, wid = tid >> 5;
    const int wm = wid >> 2, wn = wid & 3;
    const int cB = wm * 64, mB = wn * 32;
    const int q = lane >> 3, lr = lane & 7;

    float acc[4][4][4] = {};

    const int chunkc = tid & 7, rowr = tid >> 3;   // 8 chunks x 16B, row 0..31
    const uint32_t sbase = su(dsm);
    constexpr int Kt = N / 64;   // 64 chunks

    for (int kt = 0; kt < Kt + 2; kt++) {
        if (kt < Kt) {
            const uint32_t sb = sbase + (kt % 3) * NT_STAGE;
            const __nv_bfloat16* Vs = Vb + (size_t)(c0 + rowr) * N + kt * 64 + chunkc * 8;
            const __nv_bfloat16* Es = Eb + (size_t)(m0 + rowr) * N + kt * 64 + chunkc * 8;
#pragma unroll
            for (int r4 = 0; r4 < 4; r4++) {
                CP_ASYNC16(sb + (rowr + r4 * 32) * NT_ROW + chunkc * 16,
                           Vs + (size_t)(r4 * 32) * N);
                CP_ASYNC16(sb + NT_HALF + (rowr + r4 * 32) * NT_ROW + chunkc * 16,
                           Es + (size_t)(r4 * 32) * N);
            }
            CP_COMMIT();
        }
        if (kt >= 2) {
            if (kt < Kt)       asm volatile("cp.async.wait_group 2;\n" ::: "memory");
            else if (kt == Kt) asm volatile("cp.async.wait_group 1;\n" ::: "memory");
            else               asm volatile("cp.async.wait_group 0;\n" ::: "memory");
            __syncthreads();
            const uint32_t sb = sbase + ((kt - 2) % 3) * NT_STAGE;
#pragma unroll
            for (int ks = 0; ks < 4; ks++) {
                const int kk = ks * 16;
                uint32_t Af[4][4], Bf[2][4];
#pragma unroll
                for (int im = 0; im < 4; im++)
                    ldsm_x4(Af[im], sb + (cB + im * 16 + ((q & 1) << 3) + lr) * NT_ROW
                                       + (kk + ((q >> 1) << 3)) * 2);
#pragma unroll
                for (int ib = 0; ib < 2; ib++)
                    ldsm_x4(Bf[ib], sb + NT_HALF
                                       + (mB + ib * 16 + ((q >> 1) << 3) + lr) * NT_ROW
                                       + (kk + ((q & 1) << 3)) * 2);
#pragma unroll
                for (int im = 0; im < 4; im++)
#pragma unroll
                    for (int in2 = 0; in2 < 4; in2++) {
                        uint32_t bfr[2] = { Bf[in2 >> 1][(in2 & 1) * 2],
                                            Bf[in2 >> 1][(in2 & 1) * 2 + 1] };
                        mma_bf16(acc[im][in2], Af[im], bfr);
                    }
            }
            __syncthreads();   // 3-ring: protect stage rewrite next iteration
        }
    }

    const float gam = gamma[0];
    const int g = lane >> 2, tg = lane & 3;
#pragma unroll
    for (int im = 0; im < 4; im++) {
        const int gc = c0 + cB + im * 16 + g;
#pragma unroll
        for (int in2 = 0; in2 < 4; in2++) {
            const int gm = m0 + mB + in2 * 8 + tg * 2;
            {
                const size_t idx = (size_t)gc * N + gm;
                const float2 xv = *reinterpret_cast<const float2*>(xb + idx);
                *reinterpret_cast<float2*>(ob + idx) =
                    make_float2(gam * acc[im][in2][0] + xv.x, gam * acc[im][in2][1] + xv.y);
            }
            {
                const size_t idx = (size_t)(gc + 8) * N + gm;
                const float2 xv = *reinterpret_cast<const float2*>(xb + idx);
                *reinterpret_cast<float2*>(ob + idx) =
                    make_float2(gam * acc[im][in2][2] + xv.x, gam * acc[im][in2][3] + xv.y);
            }
        }
    }
}

// ---------------------------------------------------------------------------
extern "C" void kernel_launch(void* const* d_in, const int* in_sizes, int n_in,
                              void* d_out, int out_size)
{
    const float* x     = (const float*)d_in[0];
    const float* Wq    = (const float*)d_in[1];
    const float* bq    = (const float*)d_in[2];
    const float* Wk    = (const float*)d_in[3];
    const float* bk    = (const float*)d_in[4];
    const float* Wv    = (const float*)d_in[5];
    const float* bv    = (const float*)d_in[6];
    const float* gamma = (const float*)d_in[7];
    float* out = (float*)d_out;

    __nv_bfloat16 *xb, *qkvb, *Eb, *wt;
    float *bqkv;
    cudaGetSymbolAddress((void**)&xb,   g_xb);
    cudaGetSymbolAddress((void**)&qkvb, g_qkv);
    cudaGetSymbolAddress((void**)&Eb,   g_E);
    cudaGetSymbolAddress((void**)&wt,   g_Wt);
    cudaGetSymbolAddress((void**)&bqkv, g_bqkv);

    cudaFuncSetAttribute(gemm_tn_kernel<0>, cudaFuncAttributeMaxDynamicSharedMemorySize, TN_SMEM);
    cudaFuncSetAttribute(gemm_tn_kernel<1>, cudaFuncAttributeMaxDynamicSharedMemorySize, TN_SMEM);
    cudaFuncSetAttribute(gemm_nt_kernel,    cudaFuncAttributeMaxDynamicSharedMemorySize, NT_SMEM);

    // chains: 4 streams x 2 batches
    constexpr int NCHAIN = 4;
    constexpr int HB = B / NCHAIN;   // 2
    static cudaStream_t streams[NCHAIN] = {};
    static cudaEvent_t eFork = nullptr;
    static cudaEvent_t eJoin[NCHAIN] = {};
    if (streams[1] == nullptr) {
        streams[0] = (cudaStream_t)0;
        for (int i = 1; i < NCHAIN; i++)
            cudaStreamCreateWithFlags(&streams[i], cudaStreamNonBlocking);
        cudaEventCreateWithFlags(&eFork, cudaEventDisableTiming);
        for (int i = 1; i < NCHAIN; i++)
            cudaEventCreateWithFlags(&eJoin[i], cudaEventDisableTiming);
    }

    // 1. prep (main stream), then fork side streams
    prep_kernel<<<PREP_BLOCKS, 256>>>(x, Wq, Wk, Wv, bq, bk, bv);
    cudaEventRecord(eFork, 0);
    for (int i = 1; i < NCHAIN; i++)
        cudaStreamWaitEvent(streams[i], eFork, 0);

    for (int h = 0; h < NCHAIN; h++) {
        cudaStream_t st = streams[h];
        const int bbase = h * HB;
        const __nv_bfloat16* xbh  = xb   + (size_t)bbase * C * N;
        __nv_bfloat16*       qkvh = qkvb + (size_t)bbase * 512 * N;
        __nv_bfloat16*       Ebh  = Eb   + (size_t)bbase * N * N;

        // 2. merged projection: qkv[512][N] = Wt^T xb + bias
        gemm_tn_kernel<0><<<dim3(N / 128, 4, HB), 256, TN_SMEM, st>>>(
            wt, xbh, qkvh, bqkv, C, 512, N, N,
            0LL, (long long)C * N, (long long)512 * N, bbase);

        // 3. E = exp(q^T k), fused partial column sums
        gemm_tn_kernel<1><<<dim3(N / 128, N / 128, HB), 256, TN_SMEM, st>>>(
            qkvh, qkvh + (size_t)CQ * N, Ebh, nullptr, CQ, N, N, N,
            (long long)512 * N, (long long)512 * N, (long long)N * N, bbase);

        // 4. cinv + fold into V
        finalize_v_kernel<<<dim3(N / 128, 4, HB), 256, 0, st>>>(bbase);

        // 5. out = gamma * V' E^T + x
        gemm_nt_kernel<<<dim3(N / 128, C / 128, HB), 256, NT_SMEM, st>>>(
            x, gamma, out, bbase);
    }

    // join side chains back into the main (capture) stream
    for (int i = 1; i < NCHAIN; i++) {
        cudaEventRecord(eJoin[i], streams[i]);
        cudaStreamWaitEvent((cudaStream_t)0, eJoin[i], 0);
    }
}

// round 15
// speedup vs baseline: 1.0083x; 1.0083x over previous
#include <cuda_runtime.h>
#include <cuda_bf16.h>
#include <cstdint>

// Problem constants
constexpr int B  = 8;
constexpr int C  = 256;
constexpr int CQ = 128;
constexpr int N  = 4096;   // 64*64

// Scratch (device globals)
__device__ __align__(16) __nv_bfloat16 g_xb[B * C * N];            // x bf16, c-major
__device__ __align__(16) __nv_bfloat16 g_qkv[(size_t)B * 512 * N]; // rows: 0-127 q, 128-255 k, 256-511 v
__device__ __align__(16) __nv_bfloat16 g_E[(size_t)B * N * N];     // exp(S), bf16, 268 MB
__device__ float g_part[B * 32 * N];                               // per-mblock col sums
__device__ __align__(16) __nv_bfloat16 g_Wt[C * 512];              // concat W^T [C][512]
__device__ float g_bqkv[512];

// ---------------------------------------------------------------------------
// helpers
// ---------------------------------------------------------------------------
__device__ __forceinline__ uint32_t su(const void* p) {
    return (uint32_t)__cvta_generic_to_shared(p);
}
__device__ __forceinline__ void ldsm_x4(uint32_t* d, uint32_t addr) {
    asm volatile("ldmatrix.sync.aligned.m8n8.x4.shared.b16 {%0,%1,%2,%3}, [%4];\n"
                 : "=r"(d[0]), "=r"(d[1]), "=r"(d[2]), "=r"(d[3]) : "r"(addr));
}
__device__ __forceinline__ void ldsm_x4_t(uint32_t* d, uint32_t addr) {
    asm volatile("ldmatrix.sync.aligned.m8n8.x4.trans.shared.b16 {%0,%1,%2,%3}, [%4];\n"
                 : "=r"(d[0]), "=r"(d[1]), "=r"(d[2]), "=r"(d[3]) : "r"(addr));
}
__device__ __forceinline__ void mma_bf16(float* c, const uint32_t* a, const uint32_t* b) {
    asm volatile(
        "mma.sync.aligned.m16n8k16.row.col.f32.bf16.bf16.f32 "
        "{%0,%1,%2,%3}, {%4,%5,%6,%7}, {%8,%9}, {%0,%1,%2,%3};\n"
        : "+f"(c[0]), "+f"(c[1]), "+f"(c[2]), "+f"(c[3])
        : "r"(a[0]), "r"(a[1]), "r"(a[2]), "r"(a[3]), "r"(b[0]), "r"(b[1]));
}
#define CP_ASYNC16(dst, src) \
    asm volatile("cp.async.cg.shared.global [%0], [%1], 16;\n" :: "r"(dst), "l"(src))
#define CP_COMMIT() asm volatile("cp.async.commit_group;\n" ::: "memory")

// ---------------------------------------------------------------------------
// prep_w: Wq/Wk/Wv -> concat transposed bf16 | biases -> concat  (chain-global)
// ---------------------------------------------------------------------------
constexpr int PREP_W_BLOCKS = (C * 512) / 256;       // 512

__global__ void prep_w_kernel(const float* __restrict__ Wq, const float* __restrict__ Wk,
                              const float* __restrict__ Wv,
                              const float* __restrict__ bq, const float* __restrict__ bk,
                              const float* __restrict__ bv)
{
    const int bid = blockIdx.x;
    if (bid < PREP_W_BLOCKS) {
        const int idx = bid * 256 + threadIdx.x;  // 0 .. 131071
        if (idx < 32768) {                 // Wq -> cols 0..127
            const int c = idx >> 7, o = idx & 127;
            g_Wt[c * 512 + o] = __float2bfloat16(Wq[o * C + c]);
        } else if (idx < 65536) {          // Wk -> cols 128..255
            const int j = idx - 32768;
            const int c = j >> 7, o = j & 127;
            g_Wt[c * 512 + 128 + o] = __float2bfloat16(Wk[o * C + c]);
        } else {                           // Wv -> cols 256..511
            const int j = idx - 65536;
            const int c = j >> 8, o = j & 255;
            g_Wt[c * 512 + 256 + o] = __float2bfloat16(Wv[o * C + c]);
        }
    } else {
        const int i = (bid - PREP_W_BLOCKS) * 256 + threadIdx.x;
        if (i < 512)
            g_bqkv[i] = (i < 128) ? bq[i] : (i < 256) ? bk[i - 128] : bv[i - 256];
    }
}

// ---------------------------------------------------------------------------
// convert_x: per-chain slice of x -> bf16 (float4 per thread)
// grid covers HB batches starting at b0.
// ---------------------------------------------------------------------------
__global__ void convert_x_kernel(const float* __restrict__ x, int b0)
{
    const size_t base = (size_t)b0 * C * N / 4;
    const size_t idx = base + (size_t)blockIdx.x * 256 + threadIdx.x;
    const float4 v = reinterpret_cast<const float4*>(x)[idx];
    __nv_bfloat162 h0 = __floats2bfloat162_rn(v.x, v.y);
    __nv_bfloat162 h1 = __floats2bfloat162_rn(v.z, v.w);
    reinterpret_cast<uint2*>(g_xb)[idx] =
        make_uint2(*reinterpret_cast<uint32_t*>(&h0), *reinterpret_cast<uint32_t*>(&h1));
}

// ---------------------------------------------------------------------------
// reduce partial column sums -> cinv (smem), then scale 64 v rows in place.
// grid (N/128, 4 row-groups, HB); batch = blockIdx.z + b0
// ---------------------------------------------------------------------------
__global__ __launch_bounds__(256) void finalize_v_kernel(int b0)
{
    __shared__ float s_cinv[128];
    const int b = blockIdx.z + b0;
    const int n0 = blockIdx.x * 128;
    const int r0 = blockIdx.y * 64;
    const int t = threadIdx.x;

    {
        const int col = t & 127, half = t >> 7;
        const float* p = g_part + ((size_t)b * 32 + half * 16) * N + n0 + col;
        float z = 0.f;
#pragma unroll
        for (int i = 0; i < 16; i++) z += p[(size_t)i * N];
        __shared__ float red[2][128];
        red[half][col] = z;
        __syncthreads();
        if (t < 128) s_cinv[t] = 1.0f / (red[0][t] + red[1][t]);
        __syncthreads();
    }

    __nv_bfloat16* vb = g_qkv + (size_t)b * 512 * N + (size_t)(256 + r0) * N;
    const int col32 = t & 63;
    const int rgrp = t >> 6;
    const float c0 = s_cinv[col32 * 2];
    const float c1 = s_cinv[col32 * 2 + 1];
#pragma unroll
    for (int r = rgrp; r < 64; r += 4) {
        uint32_t* p = reinterpret_cast<uint32_t*>(vb + (size_t)r * N + n0) + col32;
        const __nv_bfloat162 v = *reinterpret_cast<const __nv_bfloat162*>(p);
        *reinterpret_cast<__nv_bfloat162*>(p) =
            __floats2bfloat162_rn(__bfloat162float(v.x) * c0, __bfloat162float(v.y) * c1);
    }
}

// ---------------------------------------------------------------------------
// TN GEMM (both operands k-major), cp.async 4-stage, one sync per k-chunk.
// 256 threads, block 128x128, warps 2(m) x 4(n), warp tile 64x32, 2 blocks/SM.
// EPI 0: + bias[row], bf16 store              (merged qkv projection)
// EPI 1: exp(acc), bf16 store E, f32 partial column sums -> g_part  (QK)
// ---------------------------------------------------------------------------
constexpr int TN_STAGE = 17408;   // A 8704 + B 8704, row stride 272 B
constexpr int TN_SMEM = 4 * TN_STAGE;   // 69632

template <int EPI>
__global__ __launch_bounds__(256, 2) void gemm_tn_kernel(
    const __nv_bfloat16* __restrict__ Ag, const __nv_bfloat16* __restrict__ Bg,
    __nv_bfloat16* __restrict__ Cg, const float* __restrict__ bias,
    int K, int lda, int ldb, int ldc,
    long long sA, long long sB, long long sC, int b0)
{
    extern __shared__ __align__(16) uint8_t dsm[];
    __shared__ float s_col[2][128];

    Ag += (long long)blockIdx.z * sA;
    Bg += (long long)blockIdx.z * sB;
    Cg += (long long)blockIdx.z * sC;

    const int m0 = blockIdx.y * 128;
    const int n0 = blockIdx.x * 128;
    const int tid = threadIdx.x;
    const int lane = tid & 31, wid = tid >> 5;
    const int wm = wid >> 2, wn = wid & 3;
    const int mB = wm * 64, nB = wn * 32;
    const int q = lane >> 3, lr = lane & 7;

    float acc[4][4][4] = {};

    const int chunk = tid & 15, row = tid >> 4;   // row 0..15
    const uint32_t sbase = su(dsm);
    const int Kt = K >> 5;

    for (int kt = 0; kt < Kt + 2; kt++) {
        if (kt < Kt) {
            const uint32_t sb = sbase + (kt & 3) * TN_STAGE;
            const __nv_bfloat16* As = Ag + (size_t)(kt * 32 + row) * lda + m0 + chunk * 8;
            const __nv_bfloat16* Bs = Bg + (size_t)(kt * 32 + row) * ldb + n0 + chunk * 8;
            CP_ASYNC16(sb + row * 272 + chunk * 16, As);
            CP_ASYNC16(sb + (row + 16) * 272 + chunk * 16, As + (size_t)16 * lda);
            CP_ASYNC16(sb + 8704 + row * 272 + chunk * 16, Bs);
            CP_ASYNC16(sb + 8704 + (row + 16) * 272 + chunk * 16, Bs + (size_t)16 * ldb);
            CP_COMMIT();
        }
        if (kt >= 2) {
            if (kt < Kt)       asm volatile("cp.async.wait_group 2;\n" ::: "memory");
            else if (kt == Kt) asm volatile("cp.async.wait_group 1;\n" ::: "memory");
            else               asm volatile("cp.async.wait_group 0;\n" ::: "memory");
            __syncthreads();   // 4-stage ring: single barrier suffices
            const uint32_t sb = sbase + ((kt - 2) & 3) * TN_STAGE;
#pragma unroll
            for (int ks = 0; ks < 2; ks++) {
                const int kk = ks * 16;
                uint32_t Af[4][4], Bf[2][4];
#pragma unroll
                for (int im = 0; im < 4; im++)
                    ldsm_x4_t(Af[im], sb + (kk + ((q >> 1) << 3) + lr) * 272
                                         + (mB + im * 16 + ((q & 1) << 3)) * 2);
#pragma unroll
                for (int ib = 0; ib < 2; ib++)
                    ldsm_x4_t(Bf[ib], sb + 8704 + (kk + ((q & 1) << 3) + lr) * 272
                                         + (nB + ib * 16 + ((q >> 1) << 3)) * 2);
#pragma unroll
                for (int im = 0; im < 4; im++)
#pragma unroll
                    for (int in2 = 0; in2 < 4; in2++) {
                        uint32_t bfr[2] = { Bf[in2 >> 1][(in2 & 1) * 2],
                                            Bf[in2 >> 1][(in2 & 1) * 2 + 1] };
                        mma_bf16(acc[im][in2], Af[im], bfr);
                    }
            }
        }
    }

    const int g = lane >> 2, tg = lane & 3;

    if (EPI == 0) {
#pragma unroll
        for (int im = 0; im < 4; im++) {
            const int gm = m0 + mB + im * 16 + g;
            const float b0f = bias[gm], b1f = bias[gm + 8];
#pragma unroll
            for (int in2 = 0; in2 < 4; in2++) {
                const int col = n0 + nB + in2 * 8 + tg * 2;
                *reinterpret_cast<__nv_bfloat162*>(Cg + (size_t)gm * ldc + col) =
                    __floats2bfloat162_rn(acc[im][in2][0] + b0f, acc[im][in2][1] + b0f);
                *reinterpret_cast<__nv_bfloat162*>(Cg + (size_t)(gm + 8) * ldc + col) =
                    __floats2bfloat162_rn(acc[im][in2][2] + b1f, acc[im][in2][3] + b1f);
            }
        }
    } else {
        float s[4][2] = {};
#pragma unroll
        for (int im = 0; im < 4; im++) {
            const int gm = m0 + mB + im * 16 + g;
#pragma unroll
            for (int in2 = 0; in2 < 4; in2++) {
                const int col = n0 + nB + in2 * 8 + tg * 2;
                const float e0 = __expf(acc[im][in2][0]);
                const float e1 = __expf(acc[im][in2][1]);
                const float e2 = __expf(acc[im][in2][2]);
                const float e3 = __expf(acc[im][in2][3]);
                *reinterpret_cast<__nv_bfloat162*>(Cg + (size_t)gm * ldc + col) =
                    __floats2bfloat162_rn(e0, e1);
                *reinterpret_cast<__nv_bfloat162*>(Cg + (size_t)(gm + 8) * ldc + col) =
                    __floats2bfloat162_rn(e2, e3);
                s[in2][0] += e0 + e2;
                s[in2][1] += e1 + e3;
            }
        }
#pragma unroll
        for (int in2 = 0; in2 < 4; in2++)
#pragma unroll
            for (int j = 0; j < 2; j++) {
                float v = s[in2][j];
                v += __shfl_xor_sync(0xFFFFFFFF, v, 4);
                v += __shfl_xor_sync(0xFFFFFFFF, v, 8);
                v += __shfl_xor_sync(0xFFFFFFFF, v, 16);
                s[in2][j] = v;
            }
        if (lane < 4) {
#pragma unroll
            for (int in2 = 0; in2 < 4; in2++)
#pragma unroll
                for (int j = 0; j < 2; j++)
                    s_col[wm][nB + in2 * 8 + lane * 2 + j] = s[in2][j];
        }
        __syncthreads();
        if (tid < 128) {
            const float z = s_col[0][tid] + s_col[1][tid];
            g_part[((size_t)(blockIdx.z + b0) * 32 + blockIdx.y) * N + n0 + tid] = z;
        }
    }
}

// ---------------------------------------------------------------------------
// NT GEMM (AV): out[c][m] = gamma * sum_n V'[c][n] * E[m][n] + x[c][m]
// 256 threads, warp tile 64x32, block 128x128, BK=32, cp.async 4-stage,
// one sync per chunk. 2 blocks/SM.   (r13-proven configuration)
// ---------------------------------------------------------------------------
constexpr int NT_STAGE = 20480;   // 2 * 128*80
constexpr int NT_SMEM = 4 * NT_STAGE;   // 81920

__global__ __launch_bounds__(256, 2) void gemm_nt_kernel(
    const float* __restrict__ x, const float* __restrict__ gamma,
    float* __restrict__ out, int b0)
{
    extern __shared__ __align__(16) uint8_t dsm[];

    const int b = blockIdx.z + b0;
    const __nv_bfloat16* Vb = g_qkv + (size_t)b * 512 * N + (size_t)256 * N;
    const __nv_bfloat16* Eb = g_E + (size_t)b * N * N;
    const float* xb = x + (size_t)b * C * N;
    float* ob = out + (size_t)b * C * N;

    const int c0 = blockIdx.y * 128;
    const int m0 = blockIdx.x * 128;
    const int tid = threadIdx.x;
    const int lane = tid & 31, wid = tid >> 5;
    const int wm = wid >> 2, wn = wid & 3;
    const int cB = wm * 64, mB = wn * 32;
    const int q = lane >> 3, lr = lane & 7;

    float acc[4][4][4] = {};

    const int chunk = tid & 3, row = tid >> 2;    // row 0..63
    const uint32_t sbase = su(dsm);
    constexpr int Kt = N / 32;   // 128

    for (int kt = 0; kt < Kt + 2; kt++) {
        if (kt < Kt) {
            const uint32_t sb = sbase + (kt & 3) * NT_STAGE;
            const __nv_bfloat16* Vs = Vb + (size_t)(c0 + row) * N + kt * 32 + chunk * 8;
            const __nv_bfloat16* Es = Eb + (size_t)(m0 + row) * N + kt * 32 + chunk * 8;
            CP_ASYNC16(sb + row * 80 + chunk * 16, Vs);
            CP_ASYNC16(sb + (row + 64) * 80 + chunk * 16, Vs + (size_t)64 * N);
            CP_ASYNC16(sb + 10240 + row * 80 + chunk * 16, Es);
            CP_ASYNC16(sb + 10240 + (row + 64) * 80 + chunk * 16, Es + (size_t)64 * N);
            CP_COMMIT();
        }
        if (kt >= 2) {
            if (kt < Kt)       asm volatile("cp.async.wait_group 2;\n" ::: "memory");
            else if (kt == Kt) asm volatile("cp.async.wait_group 1;\n" ::: "memory");
            else               asm volatile("cp.async.wait_group 0;\n" ::: "memory");
            __syncthreads();   // single barrier per chunk (4-stage ring)
            const uint32_t sb = sbase + ((kt - 2) & 3) * NT_STAGE;
#pragma unroll
            for (int ks = 0; ks < 2; ks++) {
                const int kk = ks * 16;
                uint32_t Af[4][4], Bf[2][4];
#pragma unroll
                for (int im = 0; im < 4; im++)
                    ldsm_x4(Af[im], sb + (cB + im * 16 + ((q & 1) << 3) + lr) * 80
                                       + (kk + ((q >> 1) << 3)) * 2);
#pragma unroll
                for (int ib = 0; ib < 2; ib++)
                    ldsm_x4(Bf[ib], sb + 10240 + (mB + ib * 16 + ((q >> 1) << 3) + lr) * 80
                                       + (kk + ((q & 1) << 3)) * 2);
#pragma unroll
                for (int im = 0; im < 4; im++)
#pragma unroll
                    for (int in2 = 0; in2 < 4; in2++) {
                        uint32_t bfr[2] = { Bf[in2 >> 1][(in2 & 1) * 2],
                                            Bf[in2 >> 1][(in2 & 1) * 2 + 1] };
                        mma_bf16(acc[im][in2], Af[im], bfr);
                    }
            }
        }
    }

    const float gam = gamma[0];
    const int g = lane >> 2, tg = lane & 3;
#pragma unroll
    for (int im = 0; im < 4; im++) {
        const int gc = c0 + cB + im * 16 + g;
#pragma unroll
        for (int in2 = 0; in2 < 4; in2++) {
            const int gm = m0 + mB + in2 * 8 + tg * 2;
            {
                const size_t idx = (size_t)gc * N + gm;
                const float2 xv = *reinterpret_cast<const float2*>(xb + idx);
                *reinterpret_cast<float2*>(ob + idx) =
                    make_float2(gam * acc[im][in2][0] + xv.x, gam * acc[im][in2][1] + xv.y);
            }
            {
                const size_t idx = (size_t)(gc + 8) * N + gm;
                const float2 xv = *reinterpret_cast<const float2*>(xb + idx);
                *reinterpret_cast<float2*>(ob + idx) =
                    make_float2(gam * acc[im][in2][2] + xv.x, gam * acc[im][in2][3] + xv.y);
            }
        }
    }
}

// ---------------------------------------------------------------------------
extern "C" void kernel_launch(void* const* d_in, const int* in_sizes, int n_in,
                              void* d_out, int out_size)
{
    const float* x     = (const float*)d_in[0];
    const float* Wq    = (const float*)d_in[1];
    const float* bq    = (const float*)d_in[2];
    const float* Wk    = (const float*)d_in[3];
    const float* bk    = (const float*)d_in[4];
    const float* Wv    = (const float*)d_in[5];
    const float* bv    = (const float*)d_in[6];
    const float* gamma = (const float*)d_in[7];
    float* out = (float*)d_out;

    __nv_bfloat16 *xb, *qkvb, *Eb, *wt;
    float *bqkv;
    cudaGetSymbolAddress((void**)&xb,   g_xb);
    cudaGetSymbolAddress((void**)&qkvb, g_qkv);
    cudaGetSymbolAddress((void**)&Eb,   g_E);
    cudaGetSymbolAddress((void**)&wt,   g_Wt);
    cudaGetSymbolAddress((void**)&bqkv, g_bqkv);

    cudaFuncSetAttribute(gemm_tn_kernel<0>, cudaFuncAttributeMaxDynamicSharedMemorySize, TN_SMEM);
    cudaFuncSetAttribute(gemm_tn_kernel<1>, cudaFuncAttributeMaxDynamicSharedMemorySize, TN_SMEM);
    cudaFuncSetAttribute(gemm_nt_kernel,    cudaFuncAttributeMaxDynamicSharedMemorySize, NT_SMEM);

    // chains: 4 streams x 2 batches
    constexpr int NCHAIN = 4;
    constexpr int HB = B / NCHAIN;   // 2
    static cudaStream_t streams[NCHAIN] = {};
    static cudaEvent_t eFork = nullptr;
    static cudaEvent_t eJoin[NCHAIN] = {};
    if (streams[1] == nullptr) {
        streams[0] = (cudaStream_t)0;
        for (int i = 1; i < NCHAIN; i++)
            cudaStreamCreateWithFlags(&streams[i], cudaStreamNonBlocking);
        cudaEventCreateWithFlags(&eFork, cudaEventDisableTiming);
        for (int i = 1; i < NCHAIN; i++)
            cudaEventCreateWithFlags(&eJoin[i], cudaEventDisableTiming);
    }

    // 1. prep_w only on the main stream (short), then fork
    prep_w_kernel<<<PREP_W_BLOCKS + 2, 256>>>(Wq, Wk, Wv, bq, bk, bv);
    cudaEventRecord(eFork, 0);
    for (int i = 1; i < NCHAIN; i++)
        cudaStreamWaitEvent(streams[i], eFork, 0);

    constexpr int XCONV_BLOCKS = HB * C * N / 4 / 256;   // 2048 per chain

    for (int h = 0; h < NCHAIN; h++) {
        cudaStream_t st = streams[h];
        const int bbase = h * HB;
        const __nv_bfloat16* xbh  = xb   + (size_t)bbase * C * N;
        __nv_bfloat16*       qkvh = qkvb + (size_t)bbase * 512 * N;
        __nv_bfloat16*       Ebh  = Eb   + (size_t)bbase * N * N;

        // 1b. per-chain x conversion (overlaps with other chains' GEMMs)
        convert_x_kernel<<<XCONV_BLOCKS, 256, 0, st>>>(x, bbase);

        // 2. merged projection: qkv[512][N] = Wt^T xb + bias
        gemm_tn_kernel<0><<<dim3(N / 128, 4, HB), 256, TN_SMEM, st>>>(
            wt, xbh, qkvh, bqkv, C, 512, N, N,
            0LL, (long long)C * N, (long long)512 * N, bbase);

        // 3. E = exp(q^T k), fused partial column sums
        gemm_tn_kernel<1><<<dim3(N / 128, N / 128, HB), 256, TN_SMEM, st>>>(
            qkvh, qkvh + (size_t)CQ * N, Ebh, nullptr, CQ, N, N, N,
            (long long)512 * N, (long long)512 * N, (long long)N * N, bbase);

        // 4. cinv + fold into V
        finalize_v_kernel<<<dim3(N / 128, 4, HB), 256, 0, st>>>(bbase);

        // 5. out = gamma * V' E^T + x
        gemm_nt_kernel<<<dim3(N / 128, C / 128, HB), 256, NT_SMEM, st>>>(
            x, gamma, out, bbase);
    }

    // join side chains back into the main (capture) stream
    for (int i = 1; i < NCHAIN; i++) {
        cudaEventRecord(eJoin[i], streams[i]);
        cudaStreamWaitEvent((cudaStream_t)0, eJoin[i], 0);
    }
}

// round 16
// speedup vs baseline: 1.0754x; 1.0665x over previous
#include <cuda_runtime.h>
#include <cuda_bf16.h>
#include <cstdint>

// Problem constants
constexpr int B  = 8;
constexpr int C  = 256;
constexpr int CQ = 128;
constexpr int N  = 4096;   // 64*64

// Scratch (device globals)
__device__ __align__(16) __nv_bfloat16 g_xb[B * C * N];            // x bf16, c-major
__device__ __align__(16) __nv_bfloat16 g_qkv[(size_t)B * 512 * N]; // rows: 0-127 q, 128-255 k, 256-511 v
__device__ __align__(16) __nv_bfloat16 g_E[(size_t)B * N * N];     // exp(S), bf16, 268 MB
__device__ float g_part[B * 32 * N];                               // per-mblock col sums
__device__ __align__(16) __nv_bfloat16 g_Wt[C * 512];              // concat W^T [C][512]
__device__ float g_bqkv[512];

// ---------------------------------------------------------------------------
// helpers
// ---------------------------------------------------------------------------
__device__ __forceinline__ uint32_t su(const void* p) {
    return (uint32_t)__cvta_generic_to_shared(p);
}
__device__ __forceinline__ void ldsm_x4(uint32_t* d, uint32_t addr) {
    asm volatile("ldmatrix.sync.aligned.m8n8.x4.shared.b16 {%0,%1,%2,%3}, [%4];\n"
                 : "=r"(d[0]), "=r"(d[1]), "=r"(d[2]), "=r"(d[3]) : "r"(addr));
}
__device__ __forceinline__ void ldsm_x4_t(uint32_t* d, uint32_t addr) {
    asm volatile("ldmatrix.sync.aligned.m8n8.x4.trans.shared.b16 {%0,%1,%2,%3}, [%4];\n"
                 : "=r"(d[0]), "=r"(d[1]), "=r"(d[2]), "=r"(d[3]) : "r"(addr));
}
__device__ __forceinline__ void mma_bf16(float* c, const uint32_t* a, const uint32_t* b) {
    asm volatile(
        "mma.sync.aligned.m16n8k16.row.col.f32.bf16.bf16.f32 "
        "{%0,%1,%2,%3}, {%4,%5,%6,%7}, {%8,%9}, {%0,%1,%2,%3};\n"
        : "+f"(c[0]), "+f"(c[1]), "+f"(c[2]), "+f"(c[3])
        : "r"(a[0]), "r"(a[1]), "r"(a[2]), "r"(a[3]), "r"(b[0]), "r"(b[1]));
}
#define CP_ASYNC16(dst, src) \
    asm volatile("cp.async.cg.shared.global [%0], [%1], 16;\n" :: "r"(dst), "l"(src))
#define CP_COMMIT() asm volatile("cp.async.commit_group;\n" ::: "memory")

// ---------------------------------------------------------------------------
// prep_w: Wq/Wk/Wv -> concat transposed bf16 | biases -> concat  (chain-global)
// ---------------------------------------------------------------------------
constexpr int PREP_W_BLOCKS = (C * 512) / 256;       // 512

__global__ void prep_w_kernel(const float* __restrict__ Wq, const float* __restrict__ Wk,
                              const float* __restrict__ Wv,
                              const float* __restrict__ bq, const float* __restrict__ bk,
                              const float* __restrict__ bv)
{
    const int bid = blockIdx.x;
    if (bid < PREP_W_BLOCKS) {
        const int idx = bid * 256 + threadIdx.x;  // 0 .. 131071
        if (idx < 32768) {                 // Wq -> cols 0..127
            const int c = idx >> 7, o = idx & 127;
            g_Wt[c * 512 + o] = __float2bfloat16(Wq[o * C + c]);
        } else if (idx < 65536) {          // Wk -> cols 128..255
            const int j = idx - 32768;
            const int c = j >> 7, o = j & 127;
            g_Wt[c * 512 + 128 + o] = __float2bfloat16(Wk[o * C + c]);
        } else {                           // Wv -> cols 256..511
            const int j = idx - 65536;
            const int c = j >> 8, o = j & 255;
            g_Wt[c * 512 + 256 + o] = __float2bfloat16(Wv[o * C + c]);
        }
    } else {
        const int i = (bid - PREP_W_BLOCKS) * 256 + threadIdx.x;
        if (i < 512)
            g_bqkv[i] = (i < 128) ? bq[i] : (i < 256) ? bk[i - 128] : bv[i - 256];
    }
}

// ---------------------------------------------------------------------------
// convert_x: per-chain slice of x -> bf16 (float4 per thread)
// ---------------------------------------------------------------------------
__global__ void convert_x_kernel(const float* __restrict__ x, int b0)
{
    const size_t base = (size_t)b0 * C * N / 4;
    const size_t idx = base + (size_t)blockIdx.x * 256 + threadIdx.x;
    const float4 v = reinterpret_cast<const float4*>(x)[idx];
    __nv_bfloat162 h0 = __floats2bfloat162_rn(v.x, v.y);
    __nv_bfloat162 h1 = __floats2bfloat162_rn(v.z, v.w);
    reinterpret_cast<uint2*>(g_xb)[idx] =
        make_uint2(*reinterpret_cast<uint32_t*>(&h0), *reinterpret_cast<uint32_t*>(&h1));
}

// ---------------------------------------------------------------------------
// reduce partial column sums -> cinv (smem), then scale 64 v rows in place.
// ---------------------------------------------------------------------------
__global__ __launch_bounds__(256) void finalize_v_kernel(int b0)
{
    __shared__ float s_cinv[128];
    const int b = blockIdx.z + b0;
    const int n0 = blockIdx.x * 128;
    const int r0 = blockIdx.y * 64;
    const int t = threadIdx.x;

    {
        const int col = t & 127, half = t >> 7;
        const float* p = g_part + ((size_t)b * 32 + half * 16) * N + n0 + col;
        float z = 0.f;
#pragma unroll
        for (int i = 0; i < 16; i++) z += p[(size_t)i * N];
        __shared__ float red[2][128];
        red[half][col] = z;
        __syncthreads();
        if (t < 128) s_cinv[t] = 1.0f / (red[0][t] + red[1][t]);
        __syncthreads();
    }

    __nv_bfloat16* vb = g_qkv + (size_t)b * 512 * N + (size_t)(256 + r0) * N;
    const int col32 = t & 63;
    const int rgrp = t >> 6;
    const float c0 = s_cinv[col32 * 2];
    const float c1 = s_cinv[col32 * 2 + 1];
#pragma unroll
    for (int r = rgrp; r < 64; r += 4) {
        uint32_t* p = reinterpret_cast<uint32_t*>(vb + (size_t)r * N + n0) + col32;
        const __nv_bfloat162 v = *reinterpret_cast<const __nv_bfloat162*>(p);
        *reinterpret_cast<__nv_bfloat162*>(p) =
            __floats2bfloat162_rn(__bfloat162float(v.x) * c0, __bfloat162float(v.y) * c1);
    }
}

// ---------------------------------------------------------------------------
// Projection TN GEMM: cp.async 4-stage, one sync per k-chunk. (unchanged)
// 256 threads, block 128x128, warps 2(m) x 4(n), warp tile 64x32, 2 blocks/SM.
// ---------------------------------------------------------------------------
constexpr int TN_STAGE = 17408;   // A 8704 + B 8704, row stride 272 B
constexpr int TN_SMEM = 4 * TN_STAGE;   // 69632

__global__ __launch_bounds__(256, 2) void gemm_proj_kernel(
    const __nv_bfloat16* __restrict__ Ag, const __nv_bfloat16* __restrict__ Bg,
    __nv_bfloat16* __restrict__ Cg, const float* __restrict__ bias,
    int K, int lda, int ldb, int ldc,
    long long sA, long long sB, long long sC)
{
    extern __shared__ __align__(16) uint8_t dsm[];

    Ag += (long long)blockIdx.z * sA;
    Bg += (long long)blockIdx.z * sB;
    Cg += (long long)blockIdx.z * sC;

    const int m0 = blockIdx.y * 128;
    const int n0 = blockIdx.x * 128;
    const int tid = threadIdx.x;
    const int lane = tid & 31, wid = tid >> 5;
    const int wm = wid >> 2, wn = wid & 3;
    const int mB = wm * 64, nB = wn * 32;
    const int q = lane >> 3, lr = lane & 7;

    float acc[4][4][4] = {};

    const int chunk = tid & 15, row = tid >> 4;
    const uint32_t sbase = su(dsm);
    const int Kt = K >> 5;

    for (int kt = 0; kt < Kt + 2; kt++) {
        if (kt < Kt) {
            const uint32_t sb = sbase + (kt & 3) * TN_STAGE;
            const __nv_bfloat16* As = Ag + (size_t)(kt * 32 + row) * lda + m0 + chunk * 8;
            const __nv_bfloat16* Bs = Bg + (size_t)(kt * 32 + row) * ldb + n0 + chunk * 8;
            CP_ASYNC16(sb + row * 272 + chunk * 16, As);
            CP_ASYNC16(sb + (row + 16) * 272 + chunk * 16, As + (size_t)16 * lda);
            CP_ASYNC16(sb + 8704 + row * 272 + chunk * 16, Bs);
            CP_ASYNC16(sb + 8704 + (row + 16) * 272 + chunk * 16, Bs + (size_t)16 * ldb);
            CP_COMMIT();
        }
        if (kt >= 2) {
            if (kt < Kt)       asm volatile("cp.async.wait_group 2;\n" ::: "memory");
            else if (kt == Kt) asm volatile("cp.async.wait_group 1;\n" ::: "memory");
            else               asm volatile("cp.async.wait_group 0;\n" ::: "memory");
            __syncthreads();
            const uint32_t sb = sbase + ((kt - 2) & 3) * TN_STAGE;
#pragma unroll
            for (int ks = 0; ks < 2; ks++) {
                const int kk = ks * 16;
                uint32_t Af[4][4], Bf[2][4];
#pragma unroll
                for (int im = 0; im < 4; im++)
                    ldsm_x4_t(Af[im], sb + (kk + ((q >> 1) << 3) + lr) * 272
                                         + (mB + im * 16 + ((q & 1) << 3)) * 2);
#pragma unroll
                for (int ib = 0; ib < 2; ib++)
                    ldsm_x4_t(Bf[ib], sb + 8704 + (kk + ((q & 1) << 3) + lr) * 272
                                         + (nB + ib * 16 + ((q >> 1) << 3)) * 2);
#pragma unroll
                for (int im = 0; im < 4; im++)
#pragma unroll
                    for (int in2 = 0; in2 < 4; in2++) {
                        uint32_t bfr[2] = { Bf[in2 >> 1][(in2 & 1) * 2],
                                            Bf[in2 >> 1][(in2 & 1) * 2 + 1] };
                        mma_bf16(acc[im][in2], Af[im], bfr);
                    }
            }
        }
    }

    const int g = lane >> 2, tg = lane & 3;
#pragma unroll
    for (int im = 0; im < 4; im++) {
        const int gm = m0 + mB + im * 16 + g;
        const float b0f = bias[gm], b1f = bias[gm + 8];
#pragma unroll
        for (int in2 = 0; in2 < 4; in2++) {
            const int col = n0 + nB + in2 * 8 + tg * 2;
            *reinterpret_cast<__nv_bfloat162*>(Cg + (size_t)gm * ldc + col) =
                __floats2bfloat162_rn(acc[im][in2][0] + b0f, acc[im][in2][1] + b0f);
            *reinterpret_cast<__nv_bfloat162*>(Cg + (size_t)(gm + 8) * ldc + col) =
                __floats2bfloat162_rn(acc[im][in2][2] + b1f, acc[im][in2][3] + b1f);
        }
    }
}

// ---------------------------------------------------------------------------
// QK kernel: E[m][n] = exp(sum_c q[c][m] k[c][n]) + per-mblock column sums.
// K = CQ = 128 fits smem entirely. Block: 1 n-tile x 4 m-tiles (TM=4).
// B (k) loaded ONCE; A (q) double-buffered, prefetched across m-tiles.
// 256 threads, warp tile 64x32, 2 blocks/SM (smem 102 KB).
// grid (N/128, N/512, HB); batch = blockIdx.z + b0
// ---------------------------------------------------------------------------
constexpr int QK_TILE = 34816;             // 128 rows x 272 B
constexpr int QK_SMEM = 3 * QK_TILE;       // A0, A1, B = 104448
constexpr int QK_TM = 4;

__global__ __launch_bounds__(256, 2) void qk_kernel(
    const __nv_bfloat16* __restrict__ qg, const __nv_bfloat16* __restrict__ kg,
    __nv_bfloat16* __restrict__ Eg,
    long long sQK, long long sE, int b0)
{
    extern __shared__ __align__(16) uint8_t dsm[];
    __shared__ float s_col[2][128];

    const __nv_bfloat16* Ag = qg + (long long)blockIdx.z * sQK;   // q: [128 c][N]
    const __nv_bfloat16* Bg = kg + (long long)blockIdx.z * sQK;   // k: [128 c][N]
    __nv_bfloat16* Cg = Eg + (long long)blockIdx.z * sE;

    const int n0 = blockIdx.x * 128;
    const int mg0 = blockIdx.y * (128 * QK_TM);
    const int tid = threadIdx.x;
    const int lane = tid & 31, wid = tid >> 5;
    const int wm = wid >> 2, wn = wid & 3;
    const int mB = wm * 64, nB = wn * 32;
    const int q = lane >> 3, lr = lane & 7;
    const int g = lane >> 2, tg = lane & 3;

    const uint32_t sbase = su(dsm);
    const uint32_t bbuf = sbase + 2 * QK_TILE;

    const int chunk = tid & 15, row = tid >> 4;   // 16 m-col chunks x 16 k-rows

    // preload: A tile 0 + full B, one commit group
    {
        const __nv_bfloat16* As = Ag + (size_t)row * N + mg0 + chunk * 8;
        const __nv_bfloat16* Bs = Bg + (size_t)row * N + n0 + chunk * 8;
#pragma unroll
        for (int r8 = 0; r8 < 8; r8++) {
            CP_ASYNC16(sbase + (row + r8 * 16) * 272 + chunk * 16, As + (size_t)(r8 * 16) * N);
            CP_ASYNC16(bbuf + (row + r8 * 16) * 272 + chunk * 16, Bs + (size_t)(r8 * 16) * N);
        }
        CP_COMMIT();
    }

    for (int t = 0; t < QK_TM; t++) {
        const int m0 = mg0 + t * 128;
        const uint32_t abuf = sbase + (t & 1) * QK_TILE;

        asm volatile("cp.async.wait_group 0;\n" ::: "memory");
        __syncthreads();   // A[t] (and B) visible; prior tile's compute+epilogue done

        // prefetch A[t+1] into the other buffer (overlaps compute + epilogue)
        if (t + 1 < QK_TM) {
            const uint32_t anext = sbase + ((t + 1) & 1) * QK_TILE;
            const __nv_bfloat16* As = Ag + (size_t)row * N + (m0 + 128) + chunk * 8;
#pragma unroll
            for (int r8 = 0; r8 < 8; r8++)
                CP_ASYNC16(anext + (row + r8 * 16) * 272 + chunk * 16,
                           As + (size_t)(r8 * 16) * N);
            CP_COMMIT();
        }

        // compute: K = 128 = 8 k16 steps
        float acc[4][4][4] = {};
#pragma unroll
        for (int ks = 0; ks < 8; ks++) {
            const int kk = ks * 16;
            uint32_t Af[4][4], Bf[2][4];
#pragma unroll
            for (int im = 0; im < 4; im++)
                ldsm_x4_t(Af[im], abuf + (kk + ((q >> 1) << 3) + lr) * 272
                                      + (mB + im * 16 + ((q & 1) << 3)) * 2);
#pragma unroll
            for (int ib = 0; ib < 2; ib++)
                ldsm_x4_t(Bf[ib], bbuf + (kk + ((q & 1) << 3) + lr) * 272
                                      + (nB + ib * 16 + ((q >> 1) << 3)) * 2);
#pragma unroll
            for (int im = 0; im < 4; im++)
#pragma unroll
                for (int in2 = 0; in2 < 4; in2++) {
                    uint32_t bfr[2] = { Bf[in2 >> 1][(in2 & 1) * 2],
                                        Bf[in2 >> 1][(in2 & 1) * 2 + 1] };
                    mma_bf16(acc[im][in2], Af[im], bfr);
                }
        }

        // epilogue: exp + store E + partial column sums
        float s[4][2] = {};
#pragma unroll
        for (int im = 0; im < 4; im++) {
            const int gm = m0 + mB + im * 16 + g;
#pragma unroll
            for (int in2 = 0; in2 < 4; in2++) {
                const int col = n0 + nB + in2 * 8 + tg * 2;
                const float e0 = __expf(acc[im][in2][0]);
                const float e1 = __expf(acc[im][in2][1]);
                const float e2 = __expf(acc[im][in2][2]);
                const float e3 = __expf(acc[im][in2][3]);
                *reinterpret_cast<__nv_bfloat162*>(Cg + (size_t)gm * N + col) =
                    __floats2bfloat162_rn(e0, e1);
                *reinterpret_cast<__nv_bfloat162*>(Cg + (size_t)(gm + 8) * N + col) =
                    __floats2bfloat162_rn(e2, e3);
                s[in2][0] += e0 + e2;
                s[in2][1] += e1 + e3;
            }
        }
#pragma unroll
        for (int in2 = 0; in2 < 4; in2++)
#pragma unroll
            for (int j = 0; j < 2; j++) {
                float v = s[in2][j];
                v += __shfl_xor_sync(0xFFFFFFFF, v, 4);
                v += __shfl_xor_sync(0xFFFFFFFF, v, 8);
                v += __shfl_xor_sync(0xFFFFFFFF, v, 16);
                s[in2][j] = v;
            }
        if (lane < 4) {
#pragma unroll
            for (int in2 = 0; in2 < 4; in2++)
#pragma unroll
                for (int j = 0; j < 2; j++)
                    s_col[wm][nB + in2 * 8 + lane * 2 + j] = s[in2][j];
        }
        __syncthreads();
        if (tid < 128) {
            const float z = s_col[0][tid] + s_col[1][tid];
            const int mblock = blockIdx.y * QK_TM + t;
            g_part[((size_t)(blockIdx.z + b0) * 32 + mblock) * N + n0 + tid] = z;
        }
        // next iteration's top barrier protects s_col reuse and A-buffer swap
    }
}

// ---------------------------------------------------------------------------
// NT GEMM (AV): out[c][m] = gamma * sum_n V'[c][n] * E[m][n] + x[c][m]
// 256 threads, warp tile 64x32, BK=32, cp.async 4-stage, one sync/chunk.
// ---------------------------------------------------------------------------
constexpr int NT_STAGE = 20480;   // 2 * 128*80
constexpr int NT_SMEM = 4 * NT_STAGE;   // 81920

__global__ __launch_bounds__(256, 2) void gemm_nt_kernel(
    const float* __restrict__ x, const float* __restrict__ gamma,
    float* __restrict__ out, int b0)
{
    extern __shared__ __align__(16) uint8_t dsm[];

    const int b = blockIdx.z + b0;
    const __nv_bfloat16* Vb = g_qkv + (size_t)b * 512 * N + (size_t)256 * N;
    const __nv_bfloat16* Eb = g_E + (size_t)b * N * N;
    const float* xb = x + (size_t)b * C * N;
    float* ob = out + (size_t)b * C * N;

    const int c0 = blockIdx.y * 128;
    const int m0 = blockIdx.x * 128;
    const int tid = threadIdx.x;
    const int lane = tid & 31, wid = tid >> 5;
    const int wm = wid >> 2, wn = wid & 3;
    const int cB = wm * 64, mB = wn * 32;
    const int q = lane >> 3, lr = lane & 7;

    float acc[4][4][4] = {};

    const int chunk = tid & 3, row = tid >> 2;    // row 0..63
    const uint32_t sbase = su(dsm);
    constexpr int Kt = N / 32;   // 128

    for (int kt = 0; kt < Kt + 2; kt++) {
        if (kt < Kt) {
            const uint32_t sb = sbase + (kt & 3) * NT_STAGE;
            const __nv_bfloat16* Vs = Vb + (size_t)(c0 + row) * N + kt * 32 + chunk * 8;
            const __nv_bfloat16* Es = Eb + (size_t)(m0 + row) * N + kt * 32 + chunk * 8;
            CP_ASYNC16(sb + row * 80 + chunk * 16, Vs);
            CP_ASYNC16(sb + (row + 64) * 80 + chunk * 16, Vs + (size_t)64 * N);
            CP_ASYNC16(sb + 10240 + row * 80 + chunk * 16, Es);
            CP_ASYNC16(sb + 10240 + (row + 64) * 80 + chunk * 16, Es + (size_t)64 * N);
            CP_COMMIT();
        }
        if (kt >= 2) {
            if (kt < Kt)       asm volatile("cp.async.wait_group 2;\n" ::: "memory");
            else if (kt == Kt) asm volatile("cp.async.wait_group 1;\n" ::: "memory");
            else               asm volatile("cp.async.wait_group 0;\n" ::: "memory");
            __syncthreads();   // single barrier per chunk (4-stage ring)
            const uint32_t sb = sbase + ((kt - 2) & 3) * NT_STAGE;
#pragma unroll
            for (int ks = 0; ks < 2; ks++) {
                const int kk = ks * 16;
                uint32_t Af[4][4], Bf[2][4];
#pragma unroll
                for (int im = 0; im < 4; im++)
                    ldsm_x4(Af[im], sb + (cB + im * 16 + ((q & 1) << 3) + lr) * 80
                                       + (kk + ((q >> 1) << 3)) * 2);
#pragma unroll
                for (int ib = 0; ib < 2; ib++)
                    ldsm_x4(Bf[ib], sb + 10240 + (mB + ib * 16 + ((q >> 1) << 3) + lr) * 80
                                       + (kk + ((q & 1) << 3)) * 2);
#pragma unroll
                for (int im = 0; im < 4; im++)
#pragma unroll
                    for (int in2 = 0; in2 < 4; in2++) {
                        uint32_t bfr[2] = { Bf[in2 >> 1][(in2 & 1) * 2],
                                            Bf[in2 >> 1][(in2 & 1) * 2 + 1] };
                        mma_bf16(acc[im][in2], Af[im], bfr);
                    }
            }
        }
    }

    const float gam = gamma[0];
    const int g = lane >> 2, tg = lane & 3;
#pragma unroll
    for (int im = 0; im < 4; im++) {
        const int gc = c0 + cB + im * 16 + g;
#pragma unroll
        for (int in2 = 0; in2 < 4; in2++) {
            const int gm = m0 + mB + in2 * 8 + tg * 2;
            {
                const size_t idx = (size_t)gc * N + gm;
                const float2 xv = *reinterpret_cast<const float2*>(xb + idx);
                *reinterpret_cast<float2*>(ob + idx) =
                    make_float2(gam * acc[im][in2][0] + xv.x, gam * acc[im][in2][1] + xv.y);
            }
            {
                const size_t idx = (size_t)(gc + 8) * N + gm;
                const float2 xv = *reinterpret_cast<const float2*>(xb + idx);
                *reinterpret_cast<float2*>(ob + idx) =
                    make_float2(gam * acc[im][in2][2] + xv.x, gam * acc[im][in2][3] + xv.y);
            }
        }
    }
}

// ---------------------------------------------------------------------------
extern "C" void kernel_launch(void* const* d_in, const int* in_sizes, int n_in,
                              void* d_out, int out_size)
{
    const float* x     = (const float*)d_in[0];
    const float* Wq    = (const float*)d_in[1];
    const float* bq    = (const float*)d_in[2];
    const float* Wk    = (const float*)d_in[3];
    const float* bk    = (const float*)d_in[4];
    const float* Wv    = (const float*)d_in[5];
    const float* bv    = (const float*)d_in[6];
    const float* gamma = (const float*)d_in[7];
    float* out = (float*)d_out;

    __nv_bfloat16 *xb, *qkvb, *Eb, *wt;
    float *bqkv;
    cudaGetSymbolAddress((void**)&xb,   g_xb);
    cudaGetSymbolAddress((void**)&qkvb, g_qkv);
    cudaGetSymbolAddress((void**)&Eb,   g_E);
    cudaGetSymbolAddress((void**)&wt,   g_Wt);
    cudaGetSymbolAddress((void**)&bqkv, g_bqkv);

    cudaFuncSetAttribute(gemm_proj_kernel, cudaFuncAttributeMaxDynamicSharedMemorySize, TN_SMEM);
    cudaFuncSetAttribute(qk_kernel,        cudaFuncAttributeMaxDynamicSharedMemorySize, QK_SMEM);
    cudaFuncSetAttribute(gemm_nt_kernel,   cudaFuncAttributeMaxDynamicSharedMemorySize, NT_SMEM);

    // chains: 4 streams x 2 batches
    constexpr int NCHAIN = 4;
    constexpr int HB = B / NCHAIN;   // 2
    static cudaStream_t streams[NCHAIN] = {};
    static cudaEvent_t eFork = nullptr;
    static cudaEvent_t eJoin[NCHAIN] = {};
    if (streams[1] == nullptr) {
        streams[0] = (cudaStream_t)0;
        for (int i = 1; i < NCHAIN; i++)
            cudaStreamCreateWithFlags(&streams[i], cudaStreamNonBlocking);
        cudaEventCreateWithFlags(&eFork, cudaEventDisableTiming);
        for (int i = 1; i < NCHAIN; i++)
            cudaEventCreateWithFlags(&eJoin[i], cudaEventDisableTiming);
    }

    // 1. prep_w on the main stream (short), then fork
    prep_w_kernel<<<PREP_W_BLOCKS + 2, 256>>>(Wq, Wk, Wv, bq, bk, bv);
    cudaEventRecord(eFork, 0);
    for (int i = 1; i < NCHAIN; i++)
        cudaStreamWaitEvent(streams[i], eFork, 0);

    constexpr int XCONV_BLOCKS = HB * C * N / 4 / 256;   // 2048 per chain

    for (int h = 0; h < NCHAIN; h++) {
        cudaStream_t st = streams[h];
        const int bbase = h * HB;
        const __nv_bfloat16* xbh  = xb   + (size_t)bbase * C * N;
        __nv_bfloat16*       qkvh = qkvb + (size_t)bbase * 512 * N;
        __nv_bfloat16*       Ebh  = Eb   + (size_t)bbase * N * N;

        // 1b. per-chain x conversion
        convert_x_kernel<<<XCONV_BLOCKS, 256, 0, st>>>(x, bbase);

        // 2. merged projection: qkv[512][N] = Wt^T xb + bias
        gemm_proj_kernel<<<dim3(N / 128, 4, HB), 256, TN_SMEM, st>>>(
            wt, xbh, qkvh, bqkv, C, 512, N, N,
            0LL, (long long)C * N, (long long)512 * N);

        // 3. E = exp(q^T k): multi-m-tile kernel, B resident, A double-buffered
        qk_kernel<<<dim3(N / 128, N / (128 * QK_TM), HB), 256, QK_SMEM, st>>>(
            qkvh, qkvh + (size_t)CQ * N, Ebh,
            (long long)512 * N, (long long)N * N, bbase);

        // 4. cinv + fold into V
        finalize_v_kernel<<<dim3(N / 128, 4, HB), 256, 0, st>>>(bbase);

        // 5. out = gamma * V' E^T + x
        gemm_nt_kernel<<<dim3(N / 128, C / 128, HB), 256, NT_SMEM, st>>>(
            x, gamma, out, bbase);
    }

    // join side chains back into the main (capture) stream
    for (int i = 1; i < NCHAIN; i++) {
        cudaEventRecord(eJoin[i], streams[i]);
        cudaStreamWaitEvent((cudaStream_t)0, eJoin[i], 0);
    }
}

// round 17
// speedup vs baseline: 1.0770x; 1.0015x over previous
#include <cuda_runtime.h>
#include <cuda_bf16.h>
#include <cstdint>

// Problem constants
constexpr int B  = 8;
constexpr int C  = 256;
constexpr int CQ = 128;
constexpr int N  = 4096;   // 64*64

// Scratch (device globals)
__device__ __align__(16) __nv_bfloat16 g_xb[B * C * N];            // x bf16, c-major
__device__ __align__(16) __nv_bfloat16 g_qkv[(size_t)B * 512 * N]; // rows: 0-127 q, 128-255 k, 256-511 v
__device__ __align__(16) __nv_bfloat16 g_E[(size_t)B * N * N];     // exp(S), bf16, 268 MB
__device__ float g_part[B * 32 * N];                               // per-mblock col sums
__device__ __align__(16) __nv_bfloat16 g_Wt[C * 512];              // concat W^T [C][512]
__device__ float g_bqkv[512];

// ---------------------------------------------------------------------------
// helpers
// ---------------------------------------------------------------------------
__device__ __forceinline__ uint32_t su(const void* p) {
    return (uint32_t)__cvta_generic_to_shared(p);
}
__device__ __forceinline__ void ldsm_x4(uint32_t* d, uint32_t addr) {
    asm volatile("ldmatrix.sync.aligned.m8n8.x4.shared.b16 {%0,%1,%2,%3}, [%4];\n"
                 : "=r"(d[0]), "=r"(d[1]), "=r"(d[2]), "=r"(d[3]) : "r"(addr));
}
__device__ __forceinline__ void ldsm_x4_t(uint32_t* d, uint32_t addr) {
    asm volatile("ldmatrix.sync.aligned.m8n8.x4.trans.shared.b16 {%0,%1,%2,%3}, [%4];\n"
                 : "=r"(d[0]), "=r"(d[1]), "=r"(d[2]), "=r"(d[3]) : "r"(addr));
}
__device__ __forceinline__ void mma_bf16(float* c, const uint32_t* a, const uint32_t* b) {
    asm volatile(
        "mma.sync.aligned.m16n8k16.row.col.f32.bf16.bf16.f32 "
        "{%0,%1,%2,%3}, {%4,%5,%6,%7}, {%8,%9}, {%0,%1,%2,%3};\n"
        : "+f"(c[0]), "+f"(c[1]), "+f"(c[2]), "+f"(c[3])
        : "r"(a[0]), "r"(a[1]), "r"(a[2]), "r"(a[3]), "r"(b[0]), "r"(b[1]));
}
#define CP_ASYNC16(dst, src) \
    asm volatile("cp.async.cg.shared.global [%0], [%1], 16;\n" :: "r"(dst), "l"(src))
#define CP_COMMIT() asm volatile("cp.async.commit_group;\n" ::: "memory")

// ---------------------------------------------------------------------------
// prep_w: Wq/Wk/Wv -> concat transposed bf16 | biases -> concat  (chain-global)
// ---------------------------------------------------------------------------
constexpr int PREP_W_BLOCKS = (C * 512) / 256;       // 512

__global__ void prep_w_kernel(const float* __restrict__ Wq, const float* __restrict__ Wk,
                              const float* __restrict__ Wv,
                              const float* __restrict__ bq, const float* __restrict__ bk,
                              const float* __restrict__ bv)
{
    const int bid = blockIdx.x;
    if (bid < PREP_W_BLOCKS) {
        const int idx = bid * 256 + threadIdx.x;  // 0 .. 131071
        if (idx < 32768) {                 // Wq -> cols 0..127
            const int c = idx >> 7, o = idx & 127;
            g_Wt[c * 512 + o] = __float2bfloat16(Wq[o * C + c]);
        } else if (idx < 65536) {          // Wk -> cols 128..255
            const int j = idx - 32768;
            const int c = j >> 7, o = j & 127;
            g_Wt[c * 512 + 128 + o] = __float2bfloat16(Wk[o * C + c]);
        } else {                           // Wv -> cols 256..511
            const int j = idx - 65536;
            const int c = j >> 8, o = j & 255;
            g_Wt[c * 512 + 256 + o] = __float2bfloat16(Wv[o * C + c]);
        }
    } else {
        const int i = (bid - PREP_W_BLOCKS) * 256 + threadIdx.x;
        if (i < 512)
            g_bqkv[i] = (i < 128) ? bq[i] : (i < 256) ? bk[i - 128] : bv[i - 256];
    }
}

// ---------------------------------------------------------------------------
// convert_x: per-chain slice of x -> bf16 (float4 per thread)
// ---------------------------------------------------------------------------
__global__ void convert_x_kernel(const float* __restrict__ x, int b0)
{
    const size_t base = (size_t)b0 * C * N / 4;
    const size_t idx = base + (size_t)blockIdx.x * 256 + threadIdx.x;
    const float4 v = reinterpret_cast<const float4*>(x)[idx];
    __nv_bfloat162 h0 = __floats2bfloat162_rn(v.x, v.y);
    __nv_bfloat162 h1 = __floats2bfloat162_rn(v.z, v.w);
    reinterpret_cast<uint2*>(g_xb)[idx] =
        make_uint2(*reinterpret_cast<uint32_t*>(&h0), *reinterpret_cast<uint32_t*>(&h1));
}

// ---------------------------------------------------------------------------
// reduce partial column sums -> cinv (smem), then scale 64 v rows in place.
// ---------------------------------------------------------------------------
__global__ __launch_bounds__(256) void finalize_v_kernel(int b0)
{
    __shared__ float s_cinv[128];
    const int b = blockIdx.z + b0;
    const int n0 = blockIdx.x * 128;
    const int r0 = blockIdx.y * 64;
    const int t = threadIdx.x;

    {
        const int col = t & 127, half = t >> 7;
        const float* p = g_part + ((size_t)b * 32 + half * 16) * N + n0 + col;
        float z = 0.f;
#pragma unroll
        for (int i = 0; i < 16; i++) z += p[(size_t)i * N];
        __shared__ float red[2][128];
        red[half][col] = z;
        __syncthreads();
        if (t < 128) s_cinv[t] = 1.0f / (red[0][t] + red[1][t]);
        __syncthreads();
    }

    __nv_bfloat16* vb = g_qkv + (size_t)b * 512 * N + (size_t)(256 + r0) * N;
    const int col32 = t & 63;
    const int rgrp = t >> 6;
    const float c0 = s_cinv[col32 * 2];
    const float c1 = s_cinv[col32 * 2 + 1];
#pragma unroll
    for (int r = rgrp; r < 64; r += 4) {
        uint32_t* p = reinterpret_cast<uint32_t*>(vb + (size_t)r * N + n0) + col32;
        const __nv_bfloat162 v = *reinterpret_cast<const __nv_bfloat162*>(p);
        *reinterpret_cast<__nv_bfloat162*>(p) =
            __floats2bfloat162_rn(__bfloat162float(v.x) * c0, __bfloat162float(v.y) * c1);
    }
}

// ---------------------------------------------------------------------------
// Projection TN GEMM: cp.async 4-stage, one sync per k-chunk.
// 256 threads, block 128x128, warps 2(m) x 4(n), warp tile 64x32, 2 blocks/SM.
// ---------------------------------------------------------------------------
constexpr int TN_STAGE = 17408;   // A 8704 + B 8704, row stride 272 B
constexpr int TN_SMEM = 4 * TN_STAGE;   // 69632

__global__ __launch_bounds__(256, 2) void gemm_proj_kernel(
    const __nv_bfloat16* __restrict__ Ag, const __nv_bfloat16* __restrict__ Bg,
    __nv_bfloat16* __restrict__ Cg, const float* __restrict__ bias,
    int K, int lda, int ldb, int ldc,
    long long sA, long long sB, long long sC)
{
    extern __shared__ __align__(16) uint8_t dsm[];

    Ag += (long long)blockIdx.z * sA;
    Bg += (long long)blockIdx.z * sB;
    Cg += (long long)blockIdx.z * sC;

    const int m0 = blockIdx.y * 128;
    const int n0 = blockIdx.x * 128;
    const int tid = threadIdx.x;
    const int lane = tid & 31, wid = tid >> 5;
    const int wm = wid >> 2, wn = wid & 3;
    const int mB = wm * 64, nB = wn * 32;
    const int q = lane >> 3, lr = lane & 7;

    float acc[4][4][4] = {};

    const int chunk = tid & 15, row = tid >> 4;
    const uint32_t sbase = su(dsm);
    const int Kt = K >> 5;

    for (int kt = 0; kt < Kt + 2; kt++) {
        if (kt < Kt) {
            const uint32_t sb = sbase + (kt & 3) * TN_STAGE;
            const __nv_bfloat16* As = Ag + (size_t)(kt * 32 + row) * lda + m0 + chunk * 8;
            const __nv_bfloat16* Bs = Bg + (size_t)(kt * 32 + row) * ldb + n0 + chunk * 8;
            CP_ASYNC16(sb + row * 272 + chunk * 16, As);
            CP_ASYNC16(sb + (row + 16) * 272 + chunk * 16, As + (size_t)16 * lda);
            CP_ASYNC16(sb + 8704 + row * 272 + chunk * 16, Bs);
            CP_ASYNC16(sb + 8704 + (row + 16) * 272 + chunk * 16, Bs + (size_t)16 * ldb);
            CP_COMMIT();
        }
        if (kt >= 2) {
            if (kt < Kt)       asm volatile("cp.async.wait_group 2;\n" ::: "memory");
            else if (kt == Kt) asm volatile("cp.async.wait_group 1;\n" ::: "memory");
            else               asm volatile("cp.async.wait_group 0;\n" ::: "memory");
            __syncthreads();
            const uint32_t sb = sbase + ((kt - 2) & 3) * TN_STAGE;
#pragma unroll
            for (int ks = 0; ks < 2; ks++) {
                const int kk = ks * 16;
                uint32_t Af[4][4], Bf[2][4];
#pragma unroll
                for (int im = 0; im < 4; im++)
                    ldsm_x4_t(Af[im], sb + (kk + ((q >> 1) << 3) + lr) * 272
                                         + (mB + im * 16 + ((q & 1) << 3)) * 2);
#pragma unroll
                for (int ib = 0; ib < 2; ib++)
                    ldsm_x4_t(Bf[ib], sb + 8704 + (kk + ((q & 1) << 3) + lr) * 272
                                         + (nB + ib * 16 + ((q >> 1) << 3)) * 2);
#pragma unroll
                for (int im = 0; im < 4; im++)
#pragma unroll
                    for (int in2 = 0; in2 < 4; in2++) {
                        uint32_t bfr[2] = { Bf[in2 >> 1][(in2 & 1) * 2],
                                            Bf[in2 >> 1][(in2 & 1) * 2 + 1] };
                        mma_bf16(acc[im][in2], Af[im], bfr);
                    }
            }
        }
    }

    const int g = lane >> 2, tg = lane & 3;
#pragma unroll
    for (int im = 0; im < 4; im++) {
        const int gm = m0 + mB + im * 16 + g;
        const float b0f = bias[gm], b1f = bias[gm + 8];
#pragma unroll
        for (int in2 = 0; in2 < 4; in2++) {
            const int col = n0 + nB + in2 * 8 + tg * 2;
            *reinterpret_cast<__nv_bfloat162*>(Cg + (size_t)gm * ldc + col) =
                __floats2bfloat162_rn(acc[im][in2][0] + b0f, acc[im][in2][1] + b0f);
            *reinterpret_cast<__nv_bfloat162*>(Cg + (size_t)(gm + 8) * ldc + col) =
                __floats2bfloat162_rn(acc[im][in2][2] + b1f, acc[im][in2][3] + b1f);
        }
    }
}

// ---------------------------------------------------------------------------
// QK kernel: E[m][n] = exp(sum_c q[c][m] k[c][n]) + per-mblock column sums.
// K = CQ = 128 resident in smem. Block: 1 n-tile x 8 m-tiles (TM=8) ->
// per-chain grid (32, 4, HB) = 256 blocks = ONE wave.
// B (k) loaded ONCE; A (q) double-buffered, prefetched across m-tiles.
// 256 threads, warp tile 64x32, 2 blocks/SM (smem 102 KB).
// ---------------------------------------------------------------------------
constexpr int QK_TILE = 34816;             // 128 rows x 272 B
constexpr int QK_SMEM = 3 * QK_TILE;       // A0, A1, B = 104448
constexpr int QK_TM = 8;

__global__ __launch_bounds__(256, 2) void qk_kernel(
    const __nv_bfloat16* __restrict__ qg, const __nv_bfloat16* __restrict__ kg,
    __nv_bfloat16* __restrict__ Eg,
    long long sQK, long long sE, int b0)
{
    extern __shared__ __align__(16) uint8_t dsm[];
    __shared__ float s_col[2][128];

    const __nv_bfloat16* Ag = qg + (long long)blockIdx.z * sQK;   // q: [128 c][N]
    const __nv_bfloat16* Bg = kg + (long long)blockIdx.z * sQK;   // k: [128 c][N]
    __nv_bfloat16* Cg = Eg + (long long)blockIdx.z * sE;

    const int n0 = blockIdx.x * 128;
    const int mg0 = blockIdx.y * (128 * QK_TM);
    const int tid = threadIdx.x;
    const int lane = tid & 31, wid = tid >> 5;
    const int wm = wid >> 2, wn = wid & 3;
    const int mB = wm * 64, nB = wn * 32;
    const int q = lane >> 3, lr = lane & 7;
    const int g = lane >> 2, tg = lane & 3;

    const uint32_t sbase = su(dsm);
    const uint32_t bbuf = sbase + 2 * QK_TILE;

    const int chunk = tid & 15, row = tid >> 4;   // 16 m-col chunks x 16 k-rows

    // preload: A tile 0 + full B, one commit group
    {
        const __nv_bfloat16* As = Ag + (size_t)row * N + mg0 + chunk * 8;
        const __nv_bfloat16* Bs = Bg + (size_t)row * N + n0 + chunk * 8;
#pragma unroll
        for (int r8 = 0; r8 < 8; r8++) {
            CP_ASYNC16(sbase + (row + r8 * 16) * 272 + chunk * 16, As + (size_t)(r8 * 16) * N);
            CP_ASYNC16(bbuf + (row + r8 * 16) * 272 + chunk * 16, Bs + (size_t)(r8 * 16) * N);
        }
        CP_COMMIT();
    }

    for (int t = 0; t < QK_TM; t++) {
        const int m0 = mg0 + t * 128;
        const uint32_t abuf = sbase + (t & 1) * QK_TILE;

        asm volatile("cp.async.wait_group 0;\n" ::: "memory");
        __syncthreads();   // A[t] (and B) visible; prior tile's compute+epilogue done

        // prefetch A[t+1] into the other buffer (overlaps compute + epilogue)
        if (t + 1 < QK_TM) {
            const uint32_t anext = sbase + ((t + 1) & 1) * QK_TILE;
            const __nv_bfloat16* As = Ag + (size_t)row * N + (m0 + 128) + chunk * 8;
#pragma unroll
            for (int r8 = 0; r8 < 8; r8++)
                CP_ASYNC16(anext + (row + r8 * 16) * 272 + chunk * 16,
                           As + (size_t)(r8 * 16) * N);
            CP_COMMIT();
        }

        // compute: K = 128 = 8 k16 steps
        float acc[4][4][4] = {};
#pragma unroll
        for (int ks = 0; ks < 8; ks++) {
            const int kk = ks * 16;
            uint32_t Af[4][4], Bf[2][4];
#pragma unroll
            for (int im = 0; im < 4; im++)
                ldsm_x4_t(Af[im], abuf + (kk + ((q >> 1) << 3) + lr) * 272
                                      + (mB + im * 16 + ((q & 1) << 3)) * 2);
#pragma unroll
            for (int ib = 0; ib < 2; ib++)
                ldsm_x4_t(Bf[ib], bbuf + (kk + ((q & 1) << 3) + lr) * 272
                                      + (nB + ib * 16 + ((q >> 1) << 3)) * 2);
#pragma unroll
            for (int im = 0; im < 4; im++)
#pragma unroll
                for (int in2 = 0; in2 < 4; in2++) {
                    uint32_t bfr[2] = { Bf[in2 >> 1][(in2 & 1) * 2],
                                        Bf[in2 >> 1][(in2 & 1) * 2 + 1] };
                    mma_bf16(acc[im][in2], Af[im], bfr);
                }
        }

        // epilogue: exp + store E + partial column sums
        float s[4][2] = {};
#pragma unroll
        for (int im = 0; im < 4; im++) {
            const int gm = m0 + mB + im * 16 + g;
#pragma unroll
            for (int in2 = 0; in2 < 4; in2++) {
                const int col = n0 + nB + in2 * 8 + tg * 2;
                const float e0 = __expf(acc[im][in2][0]);
                const float e1 = __expf(acc[im][in2][1]);
                const float e2 = __expf(acc[im][in2][2]);
                const float e3 = __expf(acc[im][in2][3]);
                *reinterpret_cast<__nv_bfloat162*>(Cg + (size_t)gm * N + col) =
                    __floats2bfloat162_rn(e0, e1);
                *reinterpret_cast<__nv_bfloat162*>(Cg + (size_t)(gm + 8) * N + col) =
                    __floats2bfloat162_rn(e2, e3);
                s[in2][0] += e0 + e2;
                s[in2][1] += e1 + e3;
            }
        }
#pragma unroll
        for (int in2 = 0; in2 < 4; in2++)
#pragma unroll
            for (int j = 0; j < 2; j++) {
                float v = s[in2][j];
                v += __shfl_xor_sync(0xFFFFFFFF, v, 4);
                v += __shfl_xor_sync(0xFFFFFFFF, v, 8);
                v += __shfl_xor_sync(0xFFFFFFFF, v, 16);
                s[in2][j] = v;
            }
        if (lane < 4) {
#pragma unroll
            for (int in2 = 0; in2 < 4; in2++)
#pragma unroll
                for (int j = 0; j < 2; j++)
                    s_col[wm][nB + in2 * 8 + lane * 2 + j] = s[in2][j];
        }
        __syncthreads();
        if (tid < 128) {
            const float z = s_col[0][tid] + s_col[1][tid];
            const int mblock = blockIdx.y * QK_TM + t;
            g_part[((size_t)(blockIdx.z + b0) * 32 + mblock) * N + n0 + tid] = z;
        }
        // next iteration's top barrier protects s_col reuse and A-buffer swap
    }
}

// ---------------------------------------------------------------------------
// NT GEMM (AV): out[c][m] = gamma * sum_n V'[c][n] * E[m][n] + x[c][m]
// 256 threads, warp tile 64x32, BK=32, cp.async 4-stage, one sync/chunk.
// ---------------------------------------------------------------------------
constexpr int NT_STAGE = 20480;   // 2 * 128*80
constexpr int NT_SMEM = 4 * NT_STAGE;   // 81920

__global__ __launch_bounds__(256, 2) void gemm_nt_kernel(
    const float* __restrict__ x, const float* __restrict__ gamma,
    float* __restrict__ out, int b0)
{
    extern __shared__ __align__(16) uint8_t dsm[];

    const int b = blockIdx.z + b0;
    const __nv_bfloat16* Vb = g_qkv + (size_t)b * 512 * N + (size_t)256 * N;
    const __nv_bfloat16* Eb = g_E + (size_t)b * N * N;
    const float* xb = x + (size_t)b * C * N;
    float* ob = out + (size_t)b * C * N;

    const int c0 = blockIdx.y * 128;
    const int m0 = blockIdx.x * 128;
    const int tid = threadIdx.x;
    const int lane = tid & 31, wid = tid >> 5;
    const int wm = wid >> 2, wn = wid & 3;
    const int cB = wm * 64, mB = wn * 32;
    const int q = lane >> 3, lr = lane & 7;

    float acc[4][4][4] = {};

    const int chunk = tid & 3, row = tid >> 2;    // row 0..63
    const uint32_t sbase = su(dsm);
    constexpr int Kt = N / 32;   // 128

    for (int kt = 0; kt < Kt + 2; kt++) {
        if (kt < Kt) {
            const uint32_t sb = sbase + (kt & 3) * NT_STAGE;
            const __nv_bfloat16* Vs = Vb + (size_t)(c0 + row) * N + kt * 32 + chunk * 8;
            const __nv_bfloat16* Es = Eb + (size_t)(m0 + row) * N + kt * 32 + chunk * 8;
            CP_ASYNC16(sb + row * 80 + chunk * 16, Vs);
            CP_ASYNC16(sb + (row + 64) * 80 + chunk * 16, Vs + (size_t)64 * N);
            CP_ASYNC16(sb + 10240 + row * 80 + chunk * 16, Es);
            CP_ASYNC16(sb + 10240 + (row + 64) * 80 + chunk * 16, Es + (size_t)64 * N);
            CP_COMMIT();
        }
        if (kt >= 2) {
            if (kt < Kt)       asm volatile("cp.async.wait_group 2;\n" ::: "memory");
            else if (kt == Kt) asm volatile("cp.async.wait_group 1;\n" ::: "memory");
            else               asm volatile("cp.async.wait_group 0;\n" ::: "memory");
            __syncthreads();   // single barrier per chunk (4-stage ring)
            const uint32_t sb = sbase + ((kt - 2) & 3) * NT_STAGE;
#pragma unroll
            for (int ks = 0; ks < 2; ks++) {
                const int kk = ks * 16;
                uint32_t Af[4][4], Bf[2][4];
#pragma unroll
                for (int im = 0; im < 4; im++)
                    ldsm_x4(Af[im], sb + (cB + im * 16 + ((q & 1) << 3) + lr) * 80
                                       + (kk + ((q >> 1) << 3)) * 2);
#pragma unroll
                for (int ib = 0; ib < 2; ib++)
                    ldsm_x4(Bf[ib], sb + 10240 + (mB + ib * 16 + ((q >> 1) << 3) + lr) * 80
                                       + (kk + ((q & 1) << 3)) * 2);
#pragma unroll
                for (int im = 0; im < 4; im++)
#pragma unroll
                    for (int in2 = 0; in2 < 4; in2++) {
                        uint32_t bfr[2] = { Bf[in2 >> 1][(in2 & 1) * 2],
                                            Bf[in2 >> 1][(in2 & 1) * 2 + 1] };
                        mma_bf16(acc[im][in2], Af[im], bfr);
                    }
            }
        }
    }

    const float gam = gamma[0];
    const int g = lane >> 2, tg = lane & 3;
#pragma unroll
    for (int im = 0; im < 4; im++) {
        const int gc = c0 + cB + im * 16 + g;
#pragma unroll
        for (int in2 = 0; in2 < 4; in2++) {
            const int gm = m0 + mB + in2 * 8 + tg * 2;
            {
                const size_t idx = (size_t)gc * N + gm;
                const float2 xv = *reinterpret_cast<const float2*>(xb + idx);
                *reinterpret_cast<float2*>(ob + idx) =
                    make_float2(gam * acc[im][in2][0] + xv.x, gam * acc[im][in2][1] + xv.y);
            }
            {
                const size_t idx = (size_t)(gc + 8) * N + gm;
                const float2 xv = *reinterpret_cast<const float2*>(xb + idx);
                *reinterpret_cast<float2*>(ob + idx) =
                    make_float2(gam * acc[im][in2][2] + xv.x, gam * acc[im][in2][3] + xv.y);
            }
        }
    }
}

// ---------------------------------------------------------------------------
extern "C" void kernel_launch(void* const* d_in, const int* in_sizes, int n_in,
                              void* d_out, int out_size)
{
    const float* x     = (const float*)d_in[0];
    const float* Wq    = (const float*)d_in[1];
    const float* bq    = (const float*)d_in[2];
    const float* Wk    = (const float*)d_in[3];
    const float* bk    = (const float*)d_in[4];
    const float* Wv    = (const float*)d_in[5];
    const float* bv    = (const float*)d_in[6];
    const float* gamma = (const float*)d_in[7];
    float* out = (float*)d_out;

    __nv_bfloat16 *xb, *qkvb, *Eb, *wt;
    float *bqkv;
    cudaGetSymbolAddress((void**)&xb,   g_xb);
    cudaGetSymbolAddress((void**)&qkvb, g_qkv);
    cudaGetSymbolAddress((void**)&Eb,   g_E);
    cudaGetSymbolAddress((void**)&wt,   g_Wt);
    cudaGetSymbolAddress((void**)&bqkv, g_bqkv);

    cudaFuncSetAttribute(gemm_proj_kernel, cudaFuncAttributeMaxDynamicSharedMemorySize, TN_SMEM);
    cudaFuncSetAttribute(qk_kernel,        cudaFuncAttributeMaxDynamicSharedMemorySize, QK_SMEM);
    cudaFuncSetAttribute(gemm_nt_kernel,   cudaFuncAttributeMaxDynamicSharedMemorySize, NT_SMEM);

    // chains: 4 streams x 2 batches, priority-staggered (earlier = higher prio)
    constexpr int NCHAIN = 4;
    constexpr int HB = B / NCHAIN;   // 2
    static cudaStream_t streams[NCHAIN] = {};
    static cudaEvent_t eFork = nullptr;
    static cudaEvent_t eJoin[NCHAIN] = {};
    if (streams[1] == nullptr) {
        int loPrio = 0, hiPrio = 0;
        cudaDeviceGetStreamPriorityRange(&loPrio, &hiPrio);   // hiPrio <= loPrio
        streams[0] = (cudaStream_t)0;
        for (int i = 1; i < NCHAIN; i++) {
            int prio = hiPrio + i;
            if (prio > loPrio) prio = loPrio;
            cudaStreamCreateWithPriority(&streams[i], cudaStreamNonBlocking, prio);
        }
        cudaEventCreateWithFlags(&eFork, cudaEventDisableTiming);
        for (int i = 1; i < NCHAIN; i++)
            cudaEventCreateWithFlags(&eJoin[i], cudaEventDisableTiming);
    }

    // 1. prep_w on the main stream (short), then fork
    prep_w_kernel<<<PREP_W_BLOCKS + 2, 256>>>(Wq, Wk, Wv, bq, bk, bv);
    cudaEventRecord(eFork, 0);
    for (int i = 1; i < NCHAIN; i++)
        cudaStreamWaitEvent(streams[i], eFork, 0);

    constexpr int XCONV_BLOCKS = HB * C * N / 4 / 256;   // 2048 per chain

    for (int h = 0; h < NCHAIN; h++) {
        cudaStream_t st = streams[h];
        const int bbase = h * HB;
        const __nv_bfloat16* xbh  = xb   + (size_t)bbase * C * N;
        __nv_bfloat16*       qkvh = qkvb + (size_t)bbase * 512 * N;
        __nv_bfloat16*       Ebh  = Eb   + (size_t)bbase * N * N;

        // 1b. per-chain x conversion
        convert_x_kernel<<<XCONV_BLOCKS, 256, 0, st>>>(x, bbase);

        // 2. merged projection: qkv[512][N] = Wt^T xb + bias
        gemm_proj_kernel<<<dim3(N / 128, 4, HB), 256, TN_SMEM, st>>>(
            wt, xbh, qkvh, bqkv, C, 512, N, N,
            0LL, (long long)C * N, (long long)512 * N);

        // 3. E = exp(q^T k): TM=8 multi-m-tile kernel, B resident, A dbl-buffered
        qk_kernel<<<dim3(N / 128, N / (128 * QK_TM), HB), 256, QK_SMEM, st>>>(
            qkvh, qkvh + (size_t)CQ * N, Ebh,
            (long long)512 * N, (long long)N * N, bbase);

        // 4. cinv + fold into V
        finalize_v_kernel<<<dim3(N / 128, 4, HB), 256, 0, st>>>(bbase);

        // 5. out = gamma * V' E^T + x
        gemm_nt_kernel<<<dim3(N / 128, C / 128, HB), 256, NT_SMEM, st>>>(
            x, gamma, out, bbase);
    }

    // join side chains back into the main (capture) stream
    for (int i = 1; i < NCHAIN; i++) {
        cudaEventRecord(eJoin[i], streams[i]);
        cudaStreamWaitEvent((cudaStream_t)0, eJoin[i], 0);
    }
}